// round 8
// baseline (speedup 1.0000x reference)
#include <cuda_runtime.h>

#define BB 2
#define CC 20
#define DD 256
#define WW 448
#define HWp 200704      // 448*448
#define FH 28
#define FW 28
#define FHW 784
#define KTOP 25
#define NCH 7           // pixel chunks for topk scan
#define CHPX 28672      // HWp / NCH

// ---- scratch (device globals). Invariant: zero at launch entry, re-zeroed by
// k_loss epilogue before launch exit (g_Wt/g_cv/g_ci are overwrite-before-read).
static __device__ float g_W   [BB*CC*FHW];
static __device__ float g_Wt  [BB*CC*FHW];
static __device__ int   g_cnt [BB*CC];
static __device__ int   g_done[BB*CC];
static __device__ float g_fsm [BB*CC*DD];
static __device__ float g_cv  [BB*CC*NCH*KTOP];
static __device__ int   g_ci  [BB*CC*NCH*KTOP];

// ---- pseudo-label + bilinear-weight scatter (fmax-only top-2 + rare rescan) ----
// grid = BB*196, 256 threads, 4 pixels/thread (1024 px <= 3 hi-res rows per block)
__global__ __launch_bounds__(256) void k_pseudo(
    const float* __restrict__ cam, const float* __restrict__ label,
    const float* __restrict__ hig, const float* __restrict__ low,
    const float* __restrict__ bg)
{
    __shared__ int   s_np;
    __shared__ int   s_list[CC];
    __shared__ float s_W[CC*3*30];   // [c][row 0..2][col 0..29] unclamped tile
    __shared__ int   s_cnt[CC];

    int tid = threadIdx.x;
    int b    = blockIdx.x / 196;
    int pblk = blockIdx.x % 196;
    int P0   = pblk * 1024;
    int p    = P0 + tid * 4;

    for (int i = tid; i < CC*90; i += 256) s_W[i] = 0.f;
    if (tid < CC) s_cnt[tid] = 0;
    if (tid < 32) {
        float lv = (tid < CC) ? __ldg(&label[b*CC + tid]) : 0.f;
        unsigned m = __ballot_sync(0xffffffffu, lv > 0.5f);
        if (tid < CC && lv > 0.5f) {
            int pos = __popc(m & ((1u << tid) - 1u));
            s_list[pos] = tid;
        }
        if (tid == 0) s_np = __popc(m);
    }
    __syncthreads();

    int np = s_np;
    const float* base = cam + (size_t)b * CC * HWp;

    float t1[4], t2[4];
    #pragma unroll
    for (int e = 0; e < 4; e++) { t1[e] = -1e30f; t2[e] = -1e30f; }

    for (int k = 0; k < np; k++) {
        int c = s_list[k];
        float4 v = __ldg((const float4*)(base + (size_t)c * HWp + p));
        float tm;
        tm = fminf(t1[0], v.x); t2[0] = fmaxf(t2[0], tm); t1[0] = fmaxf(t1[0], v.x);
        tm = fminf(t1[1], v.y); t2[1] = fmaxf(t2[1], tm); t1[1] = fmaxf(t1[1], v.y);
        tm = fminf(t1[2], v.z); t2[2] = fmaxf(t2[2], tm); t1[2] = fmaxf(t1[2], v.z);
        tm = fminf(t1[3], v.w); t2[3] = fmaxf(t2[3], tm); t1[3] = fmaxf(t1[3], v.w);
    }
    float Hh = __ldg(hig), Ll = __ldg(low), Gg = __ldg(bg);

    int Y0 = P0 / WW;
    int r0 = (int)floorf(((float)Y0 + 0.5f) * 0.0625f - 0.5f);

    #pragma unroll
    for (int e = 0; e < 4; e++) {
        float a = t1[e], s = t2[e];
        if (np < CC) { a = fmaxf(a, 0.f); s = fmaxf(s, 0.f); }  // absent classes are zeros
        bool lab = !(a < Hh) && !(a < Ll) && !(a < Gg) && !((a - s < 0.3f) && (a > Hh));
        lab = lab && (np > 0);
        if (lab) {
            int c = s_list[0];
            if (np > 1) {
                int pp0 = p + e;
                for (int k = 0; k < np; k++) {
                    int cc2 = s_list[k];
                    if (__ldg(&base[(size_t)cc2 * HWp + pp0]) == a) { c = cc2; break; }
                }
            }
            atomicAdd(&s_cnt[c], 1);
            int pp = p + e;
            int y = pp / WW, x = pp - y * WW;
            float sy = ((float)y + 0.5f) * 0.0625f - 0.5f;   // exact (dyadic)
            float sx = ((float)x + 0.5f) * 0.0625f - 0.5f;
            float y0f = floorf(sy), x0f = floorf(sx);
            float fy = sy - y0f,   fx = sx - x0f;
            int rr  = (int)y0f - r0;        // 0..1 (taps rr, rr+1 in [0,2])
            int c0  = (int)x0f + 1;         // 0..28
            float* tp = &s_W[c*90 + rr*30 + c0];
            atomicAdd(&tp[0],  (1.f-fy)*(1.f-fx));
            atomicAdd(&tp[1],  (1.f-fy)*fx);
            atomicAdd(&tp[30], fy*(1.f-fx));
            atomicAdd(&tp[31], fy*fx);
        }
    }
    __syncthreads();

    if (tid < CC && s_cnt[tid] > 0) atomicAdd(&g_cnt[b*CC + tid], s_cnt[tid]);
    for (int i = tid; i < CC*90; i += 256) {
        float v = s_W[i];
        if (v != 0.f) {
            int c = i / 90, rem = i - c*90;
            int rr = rem / 30, col = rem - rr*30;
            int gy = min(max(r0 + rr, 0), FH-1);
            int gx = min(max(col - 1, 0), FW-1);
            atomicAdd(&g_W[(b*CC + c)*FHW + gy*FW + gx], v);
        }
    }
}

// ---- top-25 chunk scan + fan-in merge: grid BB*CC*NCH, 256 thr ----
__global__ __launch_bounds__(256) void k_topk_scan(
    const float* __restrict__ cam, const float* __restrict__ label)
{
    int blk = blockIdx.x;
    int bc  = blk / NCH;
    int ch  = blk % NCH;
    int b = bc / CC, c = bc % CC;
    if (__ldg(&label[b*CC + c]) <= 0.5f) return;
    if (g_cnt[bc] != 0) return;

    int tid = threadIdx.x, wid = tid >> 5, lane = tid & 31;
    const float4* cp = (const float4*)(cam + ((size_t)b*CC + c) * HWp) + ch * (CHPX/4);

    float vals[KTOP]; int idxs[KTOP];   // ascending: vals[24] = max
    #pragma unroll
    for (int k = 0; k < KTOP; k++) { vals[k] = -1e30f; idxs[k] = 0x7fffffff; }
    float vmin = -1e30f;

    for (int it = 0; it < 28; it++) {
        int j = tid + it * 256;
        float4 v = __ldg(&cp[j]);
        int pbase = ch * CHPX + j * 4;
        float vv[4] = { v.x, v.y, v.z, v.w };
        #pragma unroll
        for (int e = 0; e < 4; e++) {
            float x = vv[e];
            if (x > vmin) {
                int k = 0;
                while (k < KTOP-1 && x > vals[k+1]) { vals[k] = vals[k+1]; idxs[k] = idxs[k+1]; k++; }
                vals[k] = x; idxs[k] = pbase + e;
                vmin = vals[0];
            }
        }
    }

    __shared__ float s_wv[8];
    __shared__ int   s_wi[8];
    __shared__ int   s_bi;
    int ptr = KTOP - 1;
    for (int r = 0; r < KTOP; r++) {
        float v  = (ptr >= 0) ? vals[ptr] : -1e30f;
        int   ii = (ptr >= 0) ? idxs[ptr] : 0x7fffffff;
        float mv = v; int mi = ii;
        #pragma unroll
        for (int off = 16; off > 0; off >>= 1) {
            float ov = __shfl_down_sync(0xffffffffu, mv, off);
            int   oi = __shfl_down_sync(0xffffffffu, mi, off);
            if (ov > mv || (ov == mv && oi < mi)) { mv = ov; mi = oi; }
        }
        if (lane == 0) { s_wv[wid] = mv; s_wi[wid] = mi; }
        __syncthreads();
        if (tid == 0) {
            float bv = s_wv[0]; int bi = s_wi[0];
            #pragma unroll
            for (int w = 1; w < 8; w++) {
                if (s_wv[w] > bv || (s_wv[w] == bv && s_wi[w] < bi)) { bv = s_wv[w]; bi = s_wi[w]; }
            }
            s_bi = bi;
            g_cv[blk*KTOP + r] = bv;
            g_ci[blk*KTOP + r] = bi;
        }
        __syncthreads();
        if (ptr >= 0 && idxs[ptr] == s_bi) ptr--;
    }

    // ---- fan-in: last chunk block merges the 7 lists and writes g_Wt[bc] ----
    __threadfence();
    __shared__ int s_last;
    if (tid == 0) s_last = (atomicAdd(&g_done[bc], 1) == NCH-1) ? 1 : 0;
    __syncthreads();
    if (!s_last) return;
    __threadfence();

    __shared__ float m_cv[NCH*KTOP];
    __shared__ int   m_ci[NCH*KTOP];
    __shared__ float s_wt[FHW];
    if (tid < NCH*KTOP) {
        m_cv[tid] = __ldcg(&g_cv[bc*NCH*KTOP + tid]);
        m_ci[tid] = __ldcg(&g_ci[bc*NCH*KTOP + tid]);
    }
    for (int i = tid; i < FHW; i += 256) s_wt[i] = 0.f;
    __syncthreads();

    if (tid < 32) {
        int ptr2 = 0;
        float v = -1e30f; int ii = 0x7fffffff;
        if (lane < NCH) { v = m_cv[lane*KTOP]; ii = m_ci[lane*KTOP]; }
        for (int r = 0; r < KTOP; r++) {
            float bv = v; int bi = ii;
            #pragma unroll
            for (int off = 4; off > 0; off >>= 1) {
                float ov = __shfl_xor_sync(0xffffffffu, bv, off);
                int   oi = __shfl_xor_sync(0xffffffffu, bi, off);
                if (ov > bv || (ov == bv && oi < bi)) { bv = ov; bi = oi; }
            }
            if (lane == 0) {
                int pp = bi;
                int y = pp / WW, x = pp - y * WW;
                float sy = ((float)y + 0.5f) * 0.0625f - 0.5f;
                float sx = ((float)x + 0.5f) * 0.0625f - 0.5f;
                float y0f = floorf(sy), x0f = floorf(sx);
                float fy = sy - y0f,   fx = sx - x0f;
                int y0 = (int)y0f, x0 = (int)x0f;
                int ya = min(max(y0, 0), FH-1),   yb = min(max(y0+1, 0), FH-1);
                int xa = min(max(x0, 0), FW-1),   xb = min(max(x0+1, 0), FW-1);
                s_wt[ya*FW + xa] += (1.f-fy)*(1.f-fx);
                s_wt[ya*FW + xb] += (1.f-fy)*fx;
                s_wt[yb*FW + xa] += fy*(1.f-fx);
                s_wt[yb*FW + xb] += fy*fx;
            }
            if (lane < NCH && ii == bi) {
                ptr2++;
                if (ptr2 < KTOP) { v = m_cv[lane*KTOP + ptr2]; ii = m_ci[lane*KTOP + ptr2]; }
                else             { v = -1e30f; ii = 0x7fffffff; }
            }
        }
    }
    __syncthreads();
    for (int i = tid; i < FHW; i += 256) g_Wt[bc*FHW + i] = s_wt[i];
}

// ---- fsm: grid = BB*28rows*2halves = 112 blocks, 128 thr.
//      fmap row-chunk in registers, all present-class row weights in shared ----
__global__ __launch_bounds__(128) void k_fsm(
    const float* __restrict__ fmap, const float* __restrict__ label)
{
    __shared__ int    s_np, s_nact;
    __shared__ int    s_list[CC];
    __shared__ int    s_act[CC];
    __shared__ int    s_nz[CC];
    __shared__ int    s_cnti[CC];
    __shared__ float  s_inv[CC];
    __shared__ float4 s_cw[CC][7];   // per-class row weights * inv

    int tid  = threadIdx.x;
    int half = blockIdx.x & 1;
    int row  = (blockIdx.x >> 1) % FH;
    int b    = blockIdx.x / (2*FH);

    // fmap loads first — independent of the label->cnt->weight chain
    int d = half*128 + tid;
    const float4* fr = (const float4*)(fmap + ((size_t)(b*DD + d)) * FHW + row*FW);
    float4 f[7];
    #pragma unroll
    for (int i = 0; i < 7; i++) f[i] = __ldg(&fr[i]);

    if (tid < 32) {
        float lv = (tid < CC) ? __ldg(&label[b*CC + tid]) : 0.f;
        unsigned m = __ballot_sync(0xffffffffu, lv > 0.5f);
        if (tid < CC && lv > 0.5f) s_list[__popc(m & ((1u << tid) - 1u))] = tid;
        if (tid == 0) s_np = __popc(m);
    }
    if (tid < CC) s_nz[tid] = 0;
    __syncthreads();
    int np = s_np;

    if (tid < np) {
        int bc = b*CC + s_list[tid];
        int cnt = g_cnt[bc];
        s_cnti[tid] = cnt;
        s_inv[tid]  = (cnt > 0) ? (1.f / (float)cnt) : 0.04f;
    }
    __syncthreads();

    for (int idx = tid; idx < np*7; idx += 128) {
        int k = idx / 7, q = idx - k*7;
        int bc = b*CC + s_list[k];
        const float4* src = (s_cnti[k] > 0)
            ? (const float4*)(g_W  + bc*FHW + row*FW)
            : (const float4*)(g_Wt + bc*FHW + row*FW);
        float4 v = src[q];
        float inv = s_inv[k];
        v.x *= inv; v.y *= inv; v.z *= inv; v.w *= inv;
        s_cw[k][q] = v;
        if (v.x != 0.f || v.y != 0.f || v.z != 0.f || v.w != 0.f) s_nz[k] = 1;
    }
    __syncthreads();

    if (tid < 32) {
        bool a = (tid < np) && s_nz[tid];
        unsigned m = __ballot_sync(0xffffffffu, a);
        if (a) s_act[__popc(m & ((1u << tid) - 1u))] = tid;
        if (tid == 0) s_nact = __popc(m);
    }
    __syncthreads();
    int nact = s_nact;
    if (nact == 0) return;

    for (int a = 0; a < nact; a++) {
        int k = s_act[a];
        int c = s_list[k];
        float a0 = 0.f, a1 = 0.f, a2 = 0.f, a3 = 0.f;
        #pragma unroll
        for (int i = 0; i < 7; i++) {
            float4 w = s_cw[k][i];
            a0 = fmaf(f[i].x, w.x, a0);
            a1 = fmaf(f[i].y, w.y, a1);
            a2 = fmaf(f[i].z, w.z, a2);
            a3 = fmaf(f[i].w, w.w, a3);
        }
        atomicAdd(&g_fsm[(b*CC + c)*DD + d], (a0 + a1) + (a2 + a3));
    }
}

// ---- sequential loss (1 block, 20 warps) + scratch cleanup epilogue ----
__global__ __launch_bounds__(640) void k_loss(
    const float* __restrict__ label, const float* __restrict__ proj,
    const float* __restrict__ fc0, float* __restrict__ out)
{
    __shared__ float sfsm[CC][DD];
    __shared__ float sfc [CC][DD];
    __shared__ float nf[CC], ncv[CC];
    __shared__ float cosm[CC][CC];
    __shared__ float s_term[CC];
    __shared__ int   s_q[CC];
    __shared__ float s_rowsum[CC];
    __shared__ float s_acc[2];   // [0]=loss_ccf, [1]=loss_cls

    int tid = threadIdx.x, wid = tid >> 5, lane = tid & 31;
    for (int i = tid; i < CC*DD; i += 640) (&sfc[0][0])[i] = __ldg(&fc0[i]);
    if (tid == 0) { s_acc[0] = 0.f; s_acc[1] = 0.f; }
    __syncthreads();

    for (int b = 0; b < BB; b++) {
        for (int i = tid; i < CC*DD; i += 640) (&sfsm[0][0])[i] = g_fsm[b*CC*DD + i];
        __syncthreads();

        {   // row norms (one class per warp)
            int c = wid;
            float a = 0.f, bb = 0.f;
            #pragma unroll
            for (int k = 0; k < DD/32; k++) {
                float x = sfsm[c][lane + 32*k]; a  = fmaf(x, x, a);
                float y = sfc [c][lane + 32*k]; bb = fmaf(y, y, bb);
            }
            #pragma unroll
            for (int o = 16; o > 0; o >>= 1) {
                a  += __shfl_xor_sync(0xffffffffu, a,  o);
                bb += __shfl_xor_sync(0xffffffffu, bb, o);
            }
            if (lane == 0) { nf[c] = sqrtf(a); ncv[c] = sqrtf(bb); }
        }
        __syncthreads();

        {   // cos matrix + softmax-BCE term (one class per warp)
            int c = wid;
            float rv[8];
            #pragma unroll
            for (int k = 0; k < 8; k++) rv[k] = sfsm[c][lane + 32*k];
            float invf = 1.f / fmaxf(nf[c], 1e-12f);

            float mycos = 0.f;
            #pragma unroll
            for (int j = 0; j < CC; j++) {
                float pp = 0.f;
                #pragma unroll
                for (int k = 0; k < 8; k++) pp = fmaf(rv[k], sfc[j][lane + 32*k], pp);
                #pragma unroll
                for (int o = 16; o > 0; o >>= 1) pp += __shfl_xor_sync(0xffffffffu, pp, o);
                float v = fabsf(pp * invf / fmaxf(ncv[j], 1e-12f));
                v = fminf(fmaxf(v, 1e-5f), 1.f - 1e-5f);
                if (lane == j) mycos = v;
            }
            if (lane < CC) cosm[c][lane] = mycos;

            float mylg = 0.f;
            #pragma unroll
            for (int j = 0; j < CC; j++) {
                float pp = 0.f;
                #pragma unroll
                for (int k = 0; k < 8; k++)
                    pp = fmaf(rv[k], __ldg(&proj[j*DD + lane + 32*k]), pp);
                #pragma unroll
                for (int o = 16; o > 0; o >>= 1) pp += __shfl_xor_sync(0xffffffffu, pp, o);
                if (lane == j) mylg = pp;
            }
            float x = (lane < CC) ? mylg : -3.4e38f;
            float m = x;
            #pragma unroll
            for (int o = 16; o > 0; o >>= 1) m = fmaxf(m, __shfl_xor_sync(0xffffffffu, m, o));
            float e = (lane < CC) ? expf(x - m) : 0.f;
            float ssum = e;
            #pragma unroll
            for (int o = 16; o > 0; o >>= 1) ssum += __shfl_xor_sync(0xffffffffu, ssum, o);
            float t = 0.f;
            if (lane < CC) {
                float pr = e / ssum;
                t = (lane == c) ? fmaxf(logf(pr), -100.f) : fmaxf(log1pf(-pr), -100.f);
            }
            #pragma unroll
            for (int o = 16; o > 0; o >>= 1) t += __shfl_xor_sync(0xffffffffu, t, o);
            if (lane == 0) s_term[c] = -t * (1.f / (float)CC);
        }
        __syncthreads();

        if (tid < CC) {
            int c = tid;
            bool pres = __ldg(&label[b*CC + c]) > 0.5f;
            float rs = 0.f, om = -1e30f;
            for (int j = 0; j < CC; j++) {
                float v = cosm[c][j];
                if (j == c) rs += pres ? logf(v) : log1pf(-v);
                else        { rs += log1pf(-v); om = fmaxf(om, v); }
            }
            s_rowsum[c] = rs;
            s_q[c] = (pres && om < 0.6f) ? 1 : 0;
        }
        __syncthreads();

        if (tid == 0) {
            float tot = 0.f;
            for (int c = 0; c < CC; c++) tot += s_rowsum[c];
            s_acc[0] -= tot * (1.f / (float)(CC*CC));
            float ls = 0.f; int n = 0;
            for (int c = 0; c < CC; c++) if (s_q[c]) { ls += s_term[c]; n++; }
            s_acc[1] += ls;
            if (n > 0) s_acc[1] /= (float)n;      // divides ACCUMULATED value, per reference
        }
        __syncthreads();

        for (int i = tid; i < CC*DD; i += 640) {
            int c = i >> 8;
            if (s_q[c]) (&sfc[0][0])[i] = 0.95f * (&sfc[0][0])[i] + 0.05f * (&sfsm[0][0])[i];
        }
        __syncthreads();
    }
    if (tid == 0) out[0] = s_acc[0] + s_acc[1];

    // ---- cleanup epilogue: restore zero-scratch invariant for next launch ----
    {
        float4 z4 = make_float4(0.f, 0.f, 0.f, 0.f);
        float4* w4 = (float4*)g_W;
        for (int i = tid; i < (BB*CC*FHW)/4; i += 640) w4[i] = z4;
        float4* f4 = (float4*)g_fsm;
        for (int i = tid; i < (BB*CC*DD)/4; i += 640) f4[i] = z4;
        if (tid < BB*CC) { g_cnt[tid] = 0; g_done[tid] = 0; }
    }
}

extern "C" void kernel_launch(void* const* d_in, const int* in_sizes, int n_in,
                              void* d_out, int out_size)
{
    (void)in_sizes; (void)n_in; (void)out_size;
    const float* fmap  = (const float*)d_in[0];
    const float* cam   = (const float*)d_in[1];
    const float* label = (const float*)d_in[2];
    const float* proj  = (const float*)d_in[3];
    const float* fc0   = (const float*)d_in[4];
    const float* hig   = (const float*)d_in[5];
    const float* low   = (const float*)d_in[6];
    const float* bg    = (const float*)d_in[7];
    float* out = (float*)d_out;

    k_pseudo    <<<BB*196, 256>>>(cam, label, hig, low, bg);
    k_topk_scan <<<BB*CC*NCH, 256>>>(cam, label);
    k_fsm       <<<BB*FH*2, 128>>>(fmap, label);
    k_loss      <<<1, 640>>>(label, proj, fc0, out);
}

// round 9
// speedup vs baseline: 1.1232x; 1.1232x over previous
#include <cuda_runtime.h>

#define BB 2
#define CC 20
#define DD 256
#define WW 448
#define HWp 200704      // 448*448
#define FH 28
#define FW 28
#define FHW 784
#define KTOP 25
#define NCH 7           // pixel chunks for topk scan
#define CHPX 28672      // HWp / NCH
#define SFCS 260        // padded row stride for sfc (bank-conflict avoidance, 16B-aligned)

// ---- scratch (device globals). Invariant: zero at launch entry, re-zeroed by
// k_loss epilogue before launch exit (g_Wt/g_cv/g_ci are overwrite-before-read).
static __device__ float g_W   [BB*CC*FHW];
static __device__ float g_Wt  [BB*CC*FHW];
static __device__ int   g_cnt [BB*CC];
static __device__ int   g_done[BB*CC];
static __device__ float g_fsm [BB*CC*DD];
static __device__ float g_cv  [BB*CC*NCH*KTOP];
static __device__ int   g_ci  [BB*CC*NCH*KTOP];

// ---- pseudo-label + bilinear-weight scatter (fmax-only top-2 + rare rescan) ----
__global__ __launch_bounds__(256) void k_pseudo(
    const float* __restrict__ cam, const float* __restrict__ label,
    const float* __restrict__ hig, const float* __restrict__ low,
    const float* __restrict__ bg)
{
    __shared__ int   s_np;
    __shared__ int   s_list[CC];
    __shared__ float s_W[CC*3*30];   // [c][row 0..2][col 0..29] unclamped tile
    __shared__ int   s_cnt[CC];

    int tid = threadIdx.x;
    int b    = blockIdx.x / 196;
    int pblk = blockIdx.x % 196;
    int P0   = pblk * 1024;
    int p    = P0 + tid * 4;

    for (int i = tid; i < CC*90; i += 256) s_W[i] = 0.f;
    if (tid < CC) s_cnt[tid] = 0;
    if (tid < 32) {
        float lv = (tid < CC) ? __ldg(&label[b*CC + tid]) : 0.f;
        unsigned m = __ballot_sync(0xffffffffu, lv > 0.5f);
        if (tid < CC && lv > 0.5f) {
            int pos = __popc(m & ((1u << tid) - 1u));
            s_list[pos] = tid;
        }
        if (tid == 0) s_np = __popc(m);
    }
    __syncthreads();

    int np = s_np;
    const float* base = cam + (size_t)b * CC * HWp;

    float t1[4], t2[4];
    #pragma unroll
    for (int e = 0; e < 4; e++) { t1[e] = -1e30f; t2[e] = -1e30f; }

    for (int k = 0; k < np; k++) {
        int c = s_list[k];
        float4 v = __ldg((const float4*)(base + (size_t)c * HWp + p));
        float tm;
        tm = fminf(t1[0], v.x); t2[0] = fmaxf(t2[0], tm); t1[0] = fmaxf(t1[0], v.x);
        tm = fminf(t1[1], v.y); t2[1] = fmaxf(t2[1], tm); t1[1] = fmaxf(t1[1], v.y);
        tm = fminf(t1[2], v.z); t2[2] = fmaxf(t2[2], tm); t1[2] = fmaxf(t1[2], v.z);
        tm = fminf(t1[3], v.w); t2[3] = fmaxf(t2[3], tm); t1[3] = fmaxf(t1[3], v.w);
    }
    float Hh = __ldg(hig), Ll = __ldg(low), Gg = __ldg(bg);

    int Y0 = P0 / WW;
    int r0 = (int)floorf(((float)Y0 + 0.5f) * 0.0625f - 0.5f);

    #pragma unroll
    for (int e = 0; e < 4; e++) {
        float a = t1[e], s = t2[e];
        if (np < CC) { a = fmaxf(a, 0.f); s = fmaxf(s, 0.f); }  // absent classes are zeros
        bool lab = !(a < Hh) && !(a < Ll) && !(a < Gg) && !((a - s < 0.3f) && (a > Hh));
        lab = lab && (np > 0);
        if (lab) {
            int c = s_list[0];
            if (np > 1) {
                int pp0 = p + e;
                for (int k = 0; k < np; k++) {
                    int cc2 = s_list[k];
                    if (__ldg(&base[(size_t)cc2 * HWp + pp0]) == a) { c = cc2; break; }
                }
            }
            atomicAdd(&s_cnt[c], 1);
            int pp = p + e;
            int y = pp / WW, x = pp - y * WW;
            float sy = ((float)y + 0.5f) * 0.0625f - 0.5f;   // exact (dyadic)
            float sx = ((float)x + 0.5f) * 0.0625f - 0.5f;
            float y0f = floorf(sy), x0f = floorf(sx);
            float fy = sy - y0f,   fx = sx - x0f;
            int rr  = (int)y0f - r0;        // 0..1 (taps rr, rr+1 in [0,2])
            int c0  = (int)x0f + 1;         // 0..28
            float* tp = &s_W[c*90 + rr*30 + c0];
            atomicAdd(&tp[0],  (1.f-fy)*(1.f-fx));
            atomicAdd(&tp[1],  (1.f-fy)*fx);
            atomicAdd(&tp[30], fy*(1.f-fx));
            atomicAdd(&tp[31], fy*fx);
        }
    }
    __syncthreads();

    if (tid < CC && s_cnt[tid] > 0) atomicAdd(&g_cnt[b*CC + tid], s_cnt[tid]);
    for (int i = tid; i < CC*90; i += 256) {
        float v = s_W[i];
        if (v != 0.f) {
            int c = i / 90, rem = i - c*90;
            int rr = rem / 30, col = rem - rr*30;
            int gy = min(max(r0 + rr, 0), FH-1);
            int gx = min(max(col - 1, 0), FW-1);
            atomicAdd(&g_W[(b*CC + c)*FHW + gy*FW + gx], v);
        }
    }
}

// ---- top-25 chunk scan + fan-in merge: grid BB*CC*NCH, 256 thr ----
__global__ __launch_bounds__(256) void k_topk_scan(
    const float* __restrict__ cam, const float* __restrict__ label)
{
    int blk = blockIdx.x;
    int bc  = blk / NCH;
    int ch  = blk % NCH;
    int b = bc / CC, c = bc % CC;
    if (__ldg(&label[b*CC + c]) <= 0.5f) return;
    if (g_cnt[bc] != 0) return;

    int tid = threadIdx.x, wid = tid >> 5, lane = tid & 31;
    const float4* cp = (const float4*)(cam + ((size_t)b*CC + c) * HWp) + ch * (CHPX/4);

    float vals[KTOP]; int idxs[KTOP];   // ascending: vals[24] = max
    #pragma unroll
    for (int k = 0; k < KTOP; k++) { vals[k] = -1e30f; idxs[k] = 0x7fffffff; }
    float vmin = -1e30f;

    for (int it = 0; it < 28; it++) {
        int j = tid + it * 256;
        float4 v = __ldg(&cp[j]);
        int pbase = ch * CHPX + j * 4;
        float vv[4] = { v.x, v.y, v.z, v.w };
        #pragma unroll
        for (int e = 0; e < 4; e++) {
            float x = vv[e];
            if (x > vmin) {
                int k = 0;
                while (k < KTOP-1 && x > vals[k+1]) { vals[k] = vals[k+1]; idxs[k] = idxs[k+1]; k++; }
                vals[k] = x; idxs[k] = pbase + e;
                vmin = vals[0];
            }
        }
    }

    __shared__ float s_wv[8];
    __shared__ int   s_wi[8];
    __shared__ int   s_bi;
    int ptr = KTOP - 1;
    for (int r = 0; r < KTOP; r++) {
        float v  = (ptr >= 0) ? vals[ptr] : -1e30f;
        int   ii = (ptr >= 0) ? idxs[ptr] : 0x7fffffff;
        float mv = v; int mi = ii;
        #pragma unroll
        for (int off = 16; off > 0; off >>= 1) {
            float ov = __shfl_down_sync(0xffffffffu, mv, off);
            int   oi = __shfl_down_sync(0xffffffffu, mi, off);
            if (ov > mv || (ov == mv && oi < mi)) { mv = ov; mi = oi; }
        }
        if (lane == 0) { s_wv[wid] = mv; s_wi[wid] = mi; }
        __syncthreads();
        if (tid == 0) {
            float bv = s_wv[0]; int bi = s_wi[0];
            #pragma unroll
            for (int w = 1; w < 8; w++) {
                if (s_wv[w] > bv || (s_wv[w] == bv && s_wi[w] < bi)) { bv = s_wv[w]; bi = s_wi[w]; }
            }
            s_bi = bi;
            g_cv[blk*KTOP + r] = bv;
            g_ci[blk*KTOP + r] = bi;
        }
        __syncthreads();
        if (ptr >= 0 && idxs[ptr] == s_bi) ptr--;
    }

    // ---- fan-in: last chunk block merges the 7 lists and writes g_Wt[bc] ----
    __threadfence();
    __shared__ int s_last;
    if (tid == 0) s_last = (atomicAdd(&g_done[bc], 1) == NCH-1) ? 1 : 0;
    __syncthreads();
    if (!s_last) return;
    __threadfence();

    __shared__ float m_cv[NCH*KTOP];
    __shared__ int   m_ci[NCH*KTOP];
    __shared__ float s_wt[FHW];
    if (tid < NCH*KTOP) {
        m_cv[tid] = __ldcg(&g_cv[bc*NCH*KTOP + tid]);
        m_ci[tid] = __ldcg(&g_ci[bc*NCH*KTOP + tid]);
    }
    for (int i = tid; i < FHW; i += 256) s_wt[i] = 0.f;
    __syncthreads();

    if (tid < 32) {
        int ptr2 = 0;
        float v = -1e30f; int ii = 0x7fffffff;
        if (lane < NCH) { v = m_cv[lane*KTOP]; ii = m_ci[lane*KTOP]; }
        for (int r = 0; r < KTOP; r++) {
            float bv = v; int bi = ii;
            #pragma unroll
            for (int off = 4; off > 0; off >>= 1) {
                float ov = __shfl_xor_sync(0xffffffffu, bv, off);
                int   oi = __shfl_xor_sync(0xffffffffu, bi, off);
                if (ov > bv || (ov == bv && oi < bi)) { bv = ov; bi = oi; }
            }
            if (lane == 0) {
                int pp = bi;
                int y = pp / WW, x = pp - y * WW;
                float sy = ((float)y + 0.5f) * 0.0625f - 0.5f;
                float sx = ((float)x + 0.5f) * 0.0625f - 0.5f;
                float y0f = floorf(sy), x0f = floorf(sx);
                float fy = sy - y0f,   fx = sx - x0f;
                int y0 = (int)y0f, x0 = (int)x0f;
                int ya = min(max(y0, 0), FH-1),   yb = min(max(y0+1, 0), FH-1);
                int xa = min(max(x0, 0), FW-1),   xb = min(max(x0+1, 0), FW-1);
                s_wt[ya*FW + xa] += (1.f-fy)*(1.f-fx);
                s_wt[ya*FW + xb] += (1.f-fy)*fx;
                s_wt[yb*FW + xa] += fy*(1.f-fx);
                s_wt[yb*FW + xb] += fy*fx;
            }
            if (lane < NCH && ii == bi) {
                ptr2++;
                if (ptr2 < KTOP) { v = m_cv[lane*KTOP + ptr2]; ii = m_ci[lane*KTOP + ptr2]; }
                else             { v = -1e30f; ii = 0x7fffffff; }
            }
        }
    }
    __syncthreads();
    for (int i = tid; i < FHW; i += 256) g_Wt[bc*FHW + i] = s_wt[i];
}

// ---- fsm: grid = BB*28rows*2halves = 112 blocks, 128 thr ----
__global__ __launch_bounds__(128) void k_fsm(
    const float* __restrict__ fmap, const float* __restrict__ label)
{
    __shared__ int    s_np, s_nact;
    __shared__ int    s_list[CC];
    __shared__ int    s_act[CC];
    __shared__ int    s_nz[CC];
    __shared__ int    s_cnti[CC];
    __shared__ float  s_inv[CC];
    __shared__ float4 s_cw[CC][7];

    int tid  = threadIdx.x;
    int half = blockIdx.x & 1;
    int row  = (blockIdx.x >> 1) % FH;
    int b    = blockIdx.x / (2*FH);

    int d = half*128 + tid;
    const float4* fr = (const float4*)(fmap + ((size_t)(b*DD + d)) * FHW + row*FW);
    float4 f[7];
    #pragma unroll
    for (int i = 0; i < 7; i++) f[i] = __ldg(&fr[i]);

    if (tid < 32) {
        float lv = (tid < CC) ? __ldg(&label[b*CC + tid]) : 0.f;
        unsigned m = __ballot_sync(0xffffffffu, lv > 0.5f);
        if (tid < CC && lv > 0.5f) s_list[__popc(m & ((1u << tid) - 1u))] = tid;
        if (tid == 0) s_np = __popc(m);
    }
    if (tid < CC) s_nz[tid] = 0;
    __syncthreads();
    int np = s_np;

    if (tid < np) {
        int bc = b*CC + s_list[tid];
        int cnt = g_cnt[bc];
        s_cnti[tid] = cnt;
        s_inv[tid]  = (cnt > 0) ? (1.f / (float)cnt) : 0.04f;
    }
    __syncthreads();

    for (int idx = tid; idx < np*7; idx += 128) {
        int k = idx / 7, q = idx - k*7;
        int bc = b*CC + s_list[k];
        const float4* src = (s_cnti[k] > 0)
            ? (const float4*)(g_W  + bc*FHW + row*FW)
            : (const float4*)(g_Wt + bc*FHW + row*FW);
        float4 v = src[q];
        float inv = s_inv[k];
        v.x *= inv; v.y *= inv; v.z *= inv; v.w *= inv;
        s_cw[k][q] = v;
        if (v.x != 0.f || v.y != 0.f || v.z != 0.f || v.w != 0.f) s_nz[k] = 1;
    }
    __syncthreads();

    if (tid < 32) {
        bool a = (tid < np) && s_nz[tid];
        unsigned m = __ballot_sync(0xffffffffu, a);
        if (a) s_act[__popc(m & ((1u << tid) - 1u))] = tid;
        if (tid == 0) s_nact = __popc(m);
    }
    __syncthreads();
    int nact = s_nact;
    if (nact == 0) return;

    for (int a = 0; a < nact; a++) {
        int k = s_act[a];
        int c = s_list[k];
        float a0 = 0.f, a1 = 0.f, a2 = 0.f, a3 = 0.f;
        #pragma unroll
        for (int i = 0; i < 7; i++) {
            float4 w = s_cw[k][i];
            a0 = fmaf(f[i].x, w.x, a0);
            a1 = fmaf(f[i].y, w.y, a1);
            a2 = fmaf(f[i].z, w.z, a2);
            a3 = fmaf(f[i].w, w.w, a3);
        }
        atomicAdd(&g_fsm[(b*CC + c)*DD + d], (a0 + a1) + (a2 + a3));
    }
}

// ---- sequential loss v2: transposed dots (lane = output column, no per-j
//      shuffle reductions), 20 warps, + scratch cleanup epilogue ----
__global__ __launch_bounds__(640) void k_loss(
    const float* __restrict__ label, const float* __restrict__ proj,
    const float* __restrict__ fc0, float* __restrict__ out)
{
    __shared__ __align__(16) float sfsm[CC*DD];     // fsm rows (broadcast reads)
    __shared__ __align__(16) float sfc [CC*SFCS];   // fc rows, padded stride 260
    __shared__ float s_cos[CC][21];   // raw cos dots
    __shared__ float s_lg [CC][21];   // raw logit dots
    __shared__ float invf[CC], invc[CC];
    __shared__ float s_term[CC];
    __shared__ int   s_q[CC];
    __shared__ float s_rowsum[CC];
    __shared__ float s_acc[2];        // [0]=loss_ccf, [1]=loss_cls

    int tid = threadIdx.x, wid = tid >> 5, lane = tid & 31;

    for (int i = tid; i < CC*DD; i += 640) {
        int c = i >> 8, k = i & 255;
        sfc[c*SFCS + k] = __ldg(&fc0[i]);
    }
    if (tid == 0) { s_acc[0] = 0.f; s_acc[1] = 0.f; }
    __syncthreads();

    for (int b = 0; b < BB; b++) {
        for (int i = tid; i < CC*DD; i += 640) sfsm[i] = g_fsm[b*CC*DD + i];
        __syncthreads();

        {   // norms (one class per warp): lanes over k, one 5-shfl chain
            int c = wid;
            float a = 0.f, bb = 0.f;
            #pragma unroll
            for (int k = 0; k < DD/32; k++) {
                float x = sfsm[c*DD + lane + 32*k];  a  = fmaf(x, x, a);
                float y = sfc [c*SFCS + lane + 32*k]; bb = fmaf(y, y, bb);
            }
            #pragma unroll
            for (int o = 16; o > 0; o >>= 1) {
                a  += __shfl_xor_sync(0xffffffffu, a,  o);
                bb += __shfl_xor_sync(0xffffffffu, bb, o);
            }
            if (lane == 0) {
                invf[c] = 1.f / fmaxf(sqrtf(a),  1e-12f);
                invc[c] = 1.f / fmaxf(sqrtf(bb), 1e-12f);
            }
        }
        __syncthreads();

        {   // dot phase: warps 0-9 -> cos rows {2w,2w+1}; warps 10-19 -> logit rows
            int j = lane;
            if (j < CC) {
                if (wid < 10) {
                    int r0 = wid*2, r1 = r0 + 1;
                    const float4* rv0 = (const float4*)&sfsm[r0*DD];
                    const float4* rv1 = (const float4*)&sfsm[r1*DD];
                    const float4* mj  = (const float4*)&sfc[j*SFCS];
                    float4 A = make_float4(0.f,0.f,0.f,0.f);
                    float4 Bv = make_float4(0.f,0.f,0.f,0.f);
                    #pragma unroll 4
                    for (int k4 = 0; k4 < DD/4; k4++) {
                        float4 m  = mj[k4];
                        float4 v0 = rv0[k4];
                        float4 v1 = rv1[k4];
                        A.x = fmaf(v0.x, m.x, A.x);  A.y = fmaf(v0.y, m.y, A.y);
                        A.z = fmaf(v0.z, m.z, A.z);  A.w = fmaf(v0.w, m.w, A.w);
                        Bv.x = fmaf(v1.x, m.x, Bv.x); Bv.y = fmaf(v1.y, m.y, Bv.y);
                        Bv.z = fmaf(v1.z, m.z, Bv.z); Bv.w = fmaf(v1.w, m.w, Bv.w);
                    }
                    s_cos[r0][j] = (A.x + A.y) + (A.z + A.w);
                    s_cos[r1][j] = (Bv.x + Bv.y) + (Bv.z + Bv.w);
                } else {
                    int r0 = (wid-10)*2, r1 = r0 + 1;
                    const float4* rv0 = (const float4*)&sfsm[r0*DD];
                    const float4* rv1 = (const float4*)&sfsm[r1*DD];
                    const float4* mj  = (const float4*)(proj + j*DD);
                    float4 A = make_float4(0.f,0.f,0.f,0.f);
                    float4 Bv = make_float4(0.f,0.f,0.f,0.f);
                    #pragma unroll 4
                    for (int k4 = 0; k4 < DD/4; k4++) {
                        float4 m  = __ldg(&mj[k4]);
                        float4 v0 = rv0[k4];
                        float4 v1 = rv1[k4];
                        A.x = fmaf(v0.x, m.x, A.x);  A.y = fmaf(v0.y, m.y, A.y);
                        A.z = fmaf(v0.z, m.z, A.z);  A.w = fmaf(v0.w, m.w, A.w);
                        Bv.x = fmaf(v1.x, m.x, Bv.x); Bv.y = fmaf(v1.y, m.y, Bv.y);
                        Bv.z = fmaf(v1.z, m.z, Bv.z); Bv.w = fmaf(v1.w, m.w, Bv.w);
                    }
                    s_lg[r0][j] = (A.x + A.y) + (A.z + A.w);
                    s_lg[r1][j] = (Bv.x + Bv.y) + (Bv.z + Bv.w);
                }
            }
        }
        __syncthreads();

        {   // per-row epilogue (warp c): clip/log/rowsum/offmax + softmax-BCE
            int c = wid;
            int j = lane;
            bool pres = __ldg(&label[b*CC + c]) > 0.5f;

            float v = 1e-5f;
            if (j < CC) {
                v = fabsf(s_cos[c][j] * invf[c] * invc[j]);
                v = fminf(fmaxf(v, 1e-5f), 1.f - 1e-5f);
            }
            float lt = 0.f, ov = -1e30f;
            if (j < CC) {
                lt = (j == c) ? (pres ? logf(v) : log1pf(-v)) : log1pf(-v);
                ov = (j == c) ? -1e30f : v;
            }
            float rs = lt, om = ov;
            #pragma unroll
            for (int o = 16; o > 0; o >>= 1) {
                rs += __shfl_xor_sync(0xffffffffu, rs, o);
                om  = fmaxf(om, __shfl_xor_sync(0xffffffffu, om, o));
            }
            if (lane == 0) {
                s_rowsum[c] = rs;
                s_q[c] = (pres && om < 0.6f) ? 1 : 0;
            }

            float x = (j < CC) ? s_lg[c][j] : -3.4e38f;
            float m = x;
            #pragma unroll
            for (int o = 16; o > 0; o >>= 1) m = fmaxf(m, __shfl_xor_sync(0xffffffffu, m, o));
            float e = (j < CC) ? expf(x - m) : 0.f;
            float ssum = e;
            #pragma unroll
            for (int o = 16; o > 0; o >>= 1) ssum += __shfl_xor_sync(0xffffffffu, ssum, o);
            float t = 0.f;
            if (j < CC) {
                float pr = e * (1.f / ssum);
                t = (j == c) ? fmaxf(logf(pr), -100.f) : fmaxf(log1pf(-pr), -100.f);
            }
            #pragma unroll
            for (int o = 16; o > 0; o >>= 1) t += __shfl_xor_sync(0xffffffffu, t, o);
            if (lane == 0) s_term[c] = -t * (1.f / (float)CC);
        }
        __syncthreads();

        if (tid == 0) {
            float tot = 0.f;
            for (int c = 0; c < CC; c++) tot += s_rowsum[c];
            s_acc[0] -= tot * (1.f / (float)(CC*CC));
            float ls = 0.f; int n = 0;
            for (int c = 0; c < CC; c++) if (s_q[c]) { ls += s_term[c]; n++; }
            s_acc[1] += ls;
            if (n > 0) s_acc[1] /= (float)n;      // divides ACCUMULATED value, per reference
        }
        __syncthreads();

        for (int i = tid; i < CC*DD; i += 640) {
            int c = i >> 8, k = i & 255;
            if (s_q[c]) sfc[c*SFCS + k] = 0.95f * sfc[c*SFCS + k] + 0.05f * sfsm[i];
        }
        __syncthreads();
    }
    if (tid == 0) out[0] = s_acc[0] + s_acc[1];

    // ---- cleanup epilogue: restore zero-scratch invariant for next launch ----
    {
        float4 z4 = make_float4(0.f, 0.f, 0.f, 0.f);
        float4* w4 = (float4*)g_W;
        for (int i = tid; i < (BB*CC*FHW)/4; i += 640) w4[i] = z4;
        float4* f4 = (float4*)g_fsm;
        for (int i = tid; i < (BB*CC*DD)/4; i += 640) f4[i] = z4;
        if (tid < BB*CC) { g_cnt[tid] = 0; g_done[tid] = 0; }
    }
}

extern "C" void kernel_launch(void* const* d_in, const int* in_sizes, int n_in,
                              void* d_out, int out_size)
{
    (void)in_sizes; (void)n_in; (void)out_size;
    const float* fmap  = (const float*)d_in[0];
    const float* cam   = (const float*)d_in[1];
    const float* label = (const float*)d_in[2];
    const float* proj  = (const float*)d_in[3];
    const float* fc0   = (const float*)d_in[4];
    const float* hig   = (const float*)d_in[5];
    const float* low   = (const float*)d_in[6];
    const float* bg    = (const float*)d_in[7];
    float* out = (float*)d_out;

    k_pseudo    <<<BB*196, 256>>>(cam, label, hig, low, bg);
    k_topk_scan <<<BB*CC*NCH, 256>>>(cam, label);
    k_fsm       <<<BB*FH*2, 128>>>(fmap, label);
    k_loss      <<<1, 640>>>(label, proj, fc0, out);
}

// round 10
// speedup vs baseline: 1.1775x; 1.0484x over previous
#include <cuda_runtime.h>

#define BB 2
#define CC 20
#define DD 256
#define WW 448
#define HWp 200704      // 448*448
#define FH 28
#define FW 28
#define FHW 784
#define KTOP 25
#define NCH 7           // pixel chunks for topk scan
#define CHPX 28672      // HWp / NCH
#define PS 260          // padded row stride in shared (bank-friendly, 16B-aligned)

// ---- scratch (device globals). Invariant: zero at launch entry, re-zeroed by
// k_loss epilogue before launch exit (g_Wt/g_cv/g_ci are overwrite-before-read).
static __device__ float g_W   [BB*CC*FHW];
static __device__ float g_Wt  [BB*CC*FHW];
static __device__ int   g_cnt [BB*CC];
static __device__ int   g_done[BB*CC];
static __device__ float g_fsm [BB*CC*DD];
static __device__ float g_cv  [BB*CC*NCH*KTOP];
static __device__ int   g_ci  [BB*CC*NCH*KTOP];

// ---- pseudo-label + bilinear-weight scatter (fmax-only top-2 + rare rescan) ----
__global__ __launch_bounds__(256) void k_pseudo(
    const float* __restrict__ cam, const float* __restrict__ label,
    const float* __restrict__ hig, const float* __restrict__ low,
    const float* __restrict__ bg)
{
    __shared__ int   s_np;
    __shared__ int   s_list[CC];
    __shared__ float s_W[CC*3*30];   // [c][row 0..2][col 0..29] unclamped tile
    __shared__ int   s_cnt[CC];

    int tid = threadIdx.x;
    int b    = blockIdx.x / 196;
    int pblk = blockIdx.x % 196;
    int P0   = pblk * 1024;
    int p    = P0 + tid * 4;

    for (int i = tid; i < CC*90; i += 256) s_W[i] = 0.f;
    if (tid < CC) s_cnt[tid] = 0;
    if (tid < 32) {
        float lv = (tid < CC) ? __ldg(&label[b*CC + tid]) : 0.f;
        unsigned m = __ballot_sync(0xffffffffu, lv > 0.5f);
        if (tid < CC && lv > 0.5f) {
            int pos = __popc(m & ((1u << tid) - 1u));
            s_list[pos] = tid;
        }
        if (tid == 0) s_np = __popc(m);
    }
    __syncthreads();

    int np = s_np;
    const float* base = cam + (size_t)b * CC * HWp;

    float t1[4], t2[4];
    #pragma unroll
    for (int e = 0; e < 4; e++) { t1[e] = -1e30f; t2[e] = -1e30f; }

    for (int k = 0; k < np; k++) {
        int c = s_list[k];
        float4 v = __ldg((const float4*)(base + (size_t)c * HWp + p));
        float tm;
        tm = fminf(t1[0], v.x); t2[0] = fmaxf(t2[0], tm); t1[0] = fmaxf(t1[0], v.x);
        tm = fminf(t1[1], v.y); t2[1] = fmaxf(t2[1], tm); t1[1] = fmaxf(t1[1], v.y);
        tm = fminf(t1[2], v.z); t2[2] = fmaxf(t2[2], tm); t1[2] = fmaxf(t1[2], v.z);
        tm = fminf(t1[3], v.w); t2[3] = fmaxf(t2[3], tm); t1[3] = fmaxf(t1[3], v.w);
    }
    float Hh = __ldg(hig), Ll = __ldg(low), Gg = __ldg(bg);

    int Y0 = P0 / WW;
    int r0 = (int)floorf(((float)Y0 + 0.5f) * 0.0625f - 0.5f);

    #pragma unroll
    for (int e = 0; e < 4; e++) {
        float a = t1[e], s = t2[e];
        if (np < CC) { a = fmaxf(a, 0.f); s = fmaxf(s, 0.f); }  // absent classes are zeros
        bool lab = !(a < Hh) && !(a < Ll) && !(a < Gg) && !((a - s < 0.3f) && (a > Hh));
        lab = lab && (np > 0);
        if (lab) {
            int c = s_list[0];
            if (np > 1) {
                int pp0 = p + e;
                for (int k = 0; k < np; k++) {
                    int cc2 = s_list[k];
                    if (__ldg(&base[(size_t)cc2 * HWp + pp0]) == a) { c = cc2; break; }
                }
            }
            atomicAdd(&s_cnt[c], 1);
            int pp = p + e;
            int y = pp / WW, x = pp - y * WW;
            float sy = ((float)y + 0.5f) * 0.0625f - 0.5f;   // exact (dyadic)
            float sx = ((float)x + 0.5f) * 0.0625f - 0.5f;
            float y0f = floorf(sy), x0f = floorf(sx);
            float fy = sy - y0f,   fx = sx - x0f;
            int rr  = (int)y0f - r0;        // 0..1 (taps rr, rr+1 in [0,2])
            int c0  = (int)x0f + 1;         // 0..28
            float* tp = &s_W[c*90 + rr*30 + c0];
            atomicAdd(&tp[0],  (1.f-fy)*(1.f-fx));
            atomicAdd(&tp[1],  (1.f-fy)*fx);
            atomicAdd(&tp[30], fy*(1.f-fx));
            atomicAdd(&tp[31], fy*fx);
        }
    }
    __syncthreads();

    if (tid < CC && s_cnt[tid] > 0) atomicAdd(&g_cnt[b*CC + tid], s_cnt[tid]);
    for (int i = tid; i < CC*90; i += 256) {
        float v = s_W[i];
        if (v != 0.f) {
            int c = i / 90, rem = i - c*90;
            int rr = rem / 30, col = rem - rr*30;
            int gy = min(max(r0 + rr, 0), FH-1);
            int gx = min(max(col - 1, 0), FW-1);
            atomicAdd(&g_W[(b*CC + c)*FHW + gy*FW + gx], v);
        }
    }
}

// ---- top-25 chunk scan + fan-in merge: grid BB*CC*NCH, 256 thr ----
__global__ __launch_bounds__(256) void k_topk_scan(
    const float* __restrict__ cam, const float* __restrict__ label)
{
    int blk = blockIdx.x;
    int bc  = blk / NCH;
    int ch  = blk % NCH;
    int b = bc / CC, c = bc % CC;
    if (__ldg(&label[b*CC + c]) <= 0.5f) return;
    if (g_cnt[bc] != 0) return;

    int tid = threadIdx.x, wid = tid >> 5, lane = tid & 31;
    const float4* cp = (const float4*)(cam + ((size_t)b*CC + c) * HWp) + ch * (CHPX/4);

    float vals[KTOP]; int idxs[KTOP];   // ascending: vals[24] = max
    #pragma unroll
    for (int k = 0; k < KTOP; k++) { vals[k] = -1e30f; idxs[k] = 0x7fffffff; }
    float vmin = -1e30f;

    for (int it = 0; it < 28; it++) {
        int j = tid + it * 256;
        float4 v = __ldg(&cp[j]);
        int pbase = ch * CHPX + j * 4;
        float vv[4] = { v.x, v.y, v.z, v.w };
        #pragma unroll
        for (int e = 0; e < 4; e++) {
            float x = vv[e];
            if (x > vmin) {
                int k = 0;
                while (k < KTOP-1 && x > vals[k+1]) { vals[k] = vals[k+1]; idxs[k] = idxs[k+1]; k++; }
                vals[k] = x; idxs[k] = pbase + e;
                vmin = vals[0];
            }
        }
    }

    __shared__ float s_wv[8];
    __shared__ int   s_wi[8];
    __shared__ int   s_bi;
    int ptr = KTOP - 1;
    for (int r = 0; r < KTOP; r++) {
        float v  = (ptr >= 0) ? vals[ptr] : -1e30f;
        int   ii = (ptr >= 0) ? idxs[ptr] : 0x7fffffff;
        float mv = v; int mi = ii;
        #pragma unroll
        for (int off = 16; off > 0; off >>= 1) {
            float ov = __shfl_down_sync(0xffffffffu, mv, off);
            int   oi = __shfl_down_sync(0xffffffffu, mi, off);
            if (ov > mv || (ov == mv && oi < mi)) { mv = ov; mi = oi; }
        }
        if (lane == 0) { s_wv[wid] = mv; s_wi[wid] = mi; }
        __syncthreads();
        if (tid == 0) {
            float bv = s_wv[0]; int bi = s_wi[0];
            #pragma unroll
            for (int w = 1; w < 8; w++) {
                if (s_wv[w] > bv || (s_wv[w] == bv && s_wi[w] < bi)) { bv = s_wv[w]; bi = s_wi[w]; }
            }
            s_bi = bi;
            g_cv[blk*KTOP + r] = bv;
            g_ci[blk*KTOP + r] = bi;
        }
        __syncthreads();
        if (ptr >= 0 && idxs[ptr] == s_bi) ptr--;
    }

    // ---- fan-in: last chunk block merges the 7 lists and writes g_Wt[bc] ----
    __threadfence();
    __shared__ int s_last;
    if (tid == 0) s_last = (atomicAdd(&g_done[bc], 1) == NCH-1) ? 1 : 0;
    __syncthreads();
    if (!s_last) return;
    __threadfence();

    __shared__ float m_cv[NCH*KTOP];
    __shared__ int   m_ci[NCH*KTOP];
    __shared__ float s_wt[FHW];
    if (tid < NCH*KTOP) {
        m_cv[tid] = __ldcg(&g_cv[bc*NCH*KTOP + tid]);
        m_ci[tid] = __ldcg(&g_ci[bc*NCH*KTOP + tid]);
    }
    for (int i = tid; i < FHW; i += 256) s_wt[i] = 0.f;
    __syncthreads();

    if (tid < 32) {
        int ptr2 = 0;
        float v = -1e30f; int ii = 0x7fffffff;
        if (lane < NCH) { v = m_cv[lane*KTOP]; ii = m_ci[lane*KTOP]; }
        for (int r = 0; r < KTOP; r++) {
            float bv = v; int bi = ii;
            #pragma unroll
            for (int off = 4; off > 0; off >>= 1) {
                float ov = __shfl_xor_sync(0xffffffffu, bv, off);
                int   oi = __shfl_xor_sync(0xffffffffu, bi, off);
                if (ov > bv || (ov == bv && oi < bi)) { bv = ov; bi = oi; }
            }
            if (lane == 0) {
                int pp = bi;
                int y = pp / WW, x = pp - y * WW;
                float sy = ((float)y + 0.5f) * 0.0625f - 0.5f;
                float sx = ((float)x + 0.5f) * 0.0625f - 0.5f;
                float y0f = floorf(sy), x0f = floorf(sx);
                float fy = sy - y0f,   fx = sx - x0f;
                int y0 = (int)y0f, x0 = (int)x0f;
                int ya = min(max(y0, 0), FH-1),   yb = min(max(y0+1, 0), FH-1);
                int xa = min(max(x0, 0), FW-1),   xb = min(max(x0+1, 0), FW-1);
                s_wt[ya*FW + xa] += (1.f-fy)*(1.f-fx);
                s_wt[ya*FW + xb] += (1.f-fy)*fx;
                s_wt[yb*FW + xa] += fy*(1.f-fx);
                s_wt[yb*FW + xb] += fy*fx;
            }
            if (lane < NCH && ii == bi) {
                ptr2++;
                if (ptr2 < KTOP) { v = m_cv[lane*KTOP + ptr2]; ii = m_ci[lane*KTOP + ptr2]; }
                else             { v = -1e30f; ii = 0x7fffffff; }
            }
        }
    }
    __syncthreads();
    for (int i = tid; i < FHW; i += 256) g_Wt[bc*FHW + i] = s_wt[i];
}

// ---- fsm: grid = BB*28rows*2halves = 112 blocks, 128 thr ----
__global__ __launch_bounds__(128) void k_fsm(
    const float* __restrict__ fmap, const float* __restrict__ label)
{
    __shared__ int    s_np, s_nact;
    __shared__ int    s_list[CC];
    __shared__ int    s_act[CC];
    __shared__ int    s_nz[CC];
    __shared__ int    s_cnti[CC];
    __shared__ float  s_inv[CC];
    __shared__ float4 s_cw[CC][7];

    int tid  = threadIdx.x;
    int half = blockIdx.x & 1;
    int row  = (blockIdx.x >> 1) % FH;
    int b    = blockIdx.x / (2*FH);

    int d = half*128 + tid;
    const float4* fr = (const float4*)(fmap + ((size_t)(b*DD + d)) * FHW + row*FW);
    float4 f[7];
    #pragma unroll
    for (int i = 0; i < 7; i++) f[i] = __ldg(&fr[i]);

    if (tid < 32) {
        float lv = (tid < CC) ? __ldg(&label[b*CC + tid]) : 0.f;
        unsigned m = __ballot_sync(0xffffffffu, lv > 0.5f);
        if (tid < CC && lv > 0.5f) s_list[__popc(m & ((1u << tid) - 1u))] = tid;
        if (tid == 0) s_np = __popc(m);
    }
    if (tid < CC) s_nz[tid] = 0;
    __syncthreads();
    int np = s_np;

    if (tid < np) {
        int bc = b*CC + s_list[tid];
        int cnt = g_cnt[bc];
        s_cnti[tid] = cnt;
        s_inv[tid]  = (cnt > 0) ? (1.f / (float)cnt) : 0.04f;
    }
    __syncthreads();

    for (int idx = tid; idx < np*7; idx += 128) {
        int k = idx / 7, q = idx - k*7;
        int bc = b*CC + s_list[k];
        const float4* src = (s_cnti[k] > 0)
            ? (const float4*)(g_W  + bc*FHW + row*FW)
            : (const float4*)(g_Wt + bc*FHW + row*FW);
        float4 v = src[q];
        float inv = s_inv[k];
        v.x *= inv; v.y *= inv; v.z *= inv; v.w *= inv;
        s_cw[k][q] = v;
        if (v.x != 0.f || v.y != 0.f || v.z != 0.f || v.w != 0.f) s_nz[k] = 1;
    }
    __syncthreads();

    if (tid < 32) {
        bool a = (tid < np) && s_nz[tid];
        unsigned m = __ballot_sync(0xffffffffu, a);
        if (a) s_act[__popc(m & ((1u << tid) - 1u))] = tid;
        if (tid == 0) s_nact = __popc(m);
    }
    __syncthreads();
    int nact = s_nact;
    if (nact == 0) return;

    for (int a = 0; a < nact; a++) {
        int k = s_act[a];
        int c = s_list[k];
        float a0 = 0.f, a1 = 0.f, a2 = 0.f, a3 = 0.f;
        #pragma unroll
        for (int i = 0; i < 7; i++) {
            float4 w = s_cw[k][i];
            a0 = fmaf(f[i].x, w.x, a0);
            a1 = fmaf(f[i].y, w.y, a1);
            a2 = fmaf(f[i].z, w.z, a2);
            a3 = fmaf(f[i].w, w.w, a3);
        }
        atomicAdd(&g_fsm[(b*CC + c)*DD + d], (a0 + a1) + (a2 + a3));
    }
}

// ---- loss v3: one fully-parallel 5-matrix dot phase + EMA-composed scalar
//      epilogues (de-serialized batches) + scratch cleanup. 1024 threads. ----
__global__ __launch_bounds__(1024) void k_loss(
    const float* __restrict__ label, const float* __restrict__ proj,
    const float* __restrict__ fc0, float* __restrict__ out)
{
    extern __shared__ float dyn[];
    float* sfc  = dyn;              // fc0 rows,  stride PS
    float* sprj = dyn + CC*PS;      // proj rows, stride PS
    float* sf0  = dyn + 2*CC*PS;    // fsm0 rows, stride PS

    __shared__ float s_M[5][CC][CC];   // 0:f0*fc0 1:f1*fc0 2:f1*f0 3:f0*proj 4:f1*proj
    __shared__ float s_ns[3][CC];      // sumsq: 0:fsm0 1:fsm1 2:fc0
    __shared__ float s_invf0[CC], s_invf1[CC], s_invc0[CC], s_invc1[CC];
    __shared__ float s_rowsum[CC], s_term[CC];
    __shared__ int   s_q[CC], s_q1[CC];
    __shared__ float s_acc[2];

    int tid = threadIdx.x, wid = tid >> 5, lane = tid & 31;

    for (int i = tid; i < CC*DD; i += 1024) {
        int j = i >> 8, k = i & 255;
        sfc [j*PS + k] = __ldg(&fc0[i]);
        sprj[j*PS + k] = __ldg(&proj[i]);
        sf0 [j*PS + k] = g_fsm[i];
    }
    if (tid == 0) { s_acc[0] = 0.f; s_acc[1] = 0.f; }
    __syncthreads();

    // ---- parallel task phase: 50 dot tasks (2 rows each) + 60 norm tasks ----
    int jj = (lane < CC) ? lane : 0;
    for (int t = wid; t < 110; t += 32) {
        if (t < 50) {
            int mat = t / 10, pr = t % 10, r0 = pr*2;
            int voff = (mat == 0 || mat == 3) ? 0 : CC;   // fsm0 vs fsm1 rows
            const float4* v0p = (const float4*)(g_fsm + (voff + r0)   * DD);
            const float4* v1p = (const float4*)(g_fsm + (voff + r0+1) * DD);
            const float* mT = (mat < 2) ? sfc : ((mat == 2) ? sf0 : sprj);
            const float4* mj = (const float4*)(mT + jj*PS);
            float a0=0.f,a1=0.f,a2=0.f,a3=0.f, b0=0.f,b1=0.f,b2=0.f,b3=0.f;
            #pragma unroll 4
            for (int k4 = 0; k4 < DD/4; k4++) {
                float4 m = mj[k4];
                float4 x = __ldg(v0p + k4);
                float4 y = __ldg(v1p + k4);
                a0 = fmaf(x.x, m.x, a0); a1 = fmaf(x.y, m.y, a1);
                a2 = fmaf(x.z, m.z, a2); a3 = fmaf(x.w, m.w, a3);
                b0 = fmaf(y.x, m.x, b0); b1 = fmaf(y.y, m.y, b1);
                b2 = fmaf(y.z, m.z, b2); b3 = fmaf(y.w, m.w, b3);
            }
            if (lane < CC) {
                s_M[mat][r0  ][lane] = (a0 + a1) + (a2 + a3);
                s_M[mat][r0+1][lane] = (b0 + b1) + (b2 + b3);
            }
        } else {
            int idx = t - 50, grp = idx / CC, row = idx % CC;
            const float* rp = (grp == 0) ? (g_fsm + row*DD)
                             : (grp == 1) ? (g_fsm + (CC + row)*DD)
                                          : (fc0 + row*DD);
            const float4* r4 = (const float4*)rp;
            float4 u = __ldg(&r4[lane*2]);
            float4 w = __ldg(&r4[lane*2 + 1]);
            float ss = u.x*u.x + u.y*u.y + u.z*u.z + u.w*u.w
                     + w.x*w.x + w.y*w.y + w.z*w.z + w.w*w.w;
            #pragma unroll
            for (int o = 16; o > 0; o >>= 1) ss += __shfl_xor_sync(0xffffffffu, ss, o);
            if (lane == 0) s_ns[grp][row] = ss;
        }
    }
    __syncthreads();

    if (tid < CC) {
        s_invf0[tid] = 1.f / fmaxf(sqrtf(s_ns[0][tid]), 1e-12f);
        s_invf1[tid] = 1.f / fmaxf(sqrtf(s_ns[1][tid]), 1e-12f);
        s_invc0[tid] = 1.f / fmaxf(sqrtf(s_ns[2][tid]), 1e-12f);
    }
    __syncthreads();

    // ---- T0: batch-0 epilogue (warp c, lane j) ----
    if (wid < CC) {
        int c = wid, j = lane;
        bool pres = __ldg(&label[c]) > 0.5f;
        float v = 1e-5f;
        if (j < CC) {
            v = fabsf(s_M[0][c][j] * s_invf0[c] * s_invc0[j]);
            v = fminf(fmaxf(v, 1e-5f), 1.f - 1e-5f);
        }
        float lt = 0.f, ov = -1e30f;
        if (j < CC) {
            lt = (j == c) ? (pres ? logf(v) : log1pf(-v)) : log1pf(-v);
            ov = (j == c) ? -1e30f : v;
        }
        float rs = lt, om = ov;
        #pragma unroll
        for (int o = 16; o > 0; o >>= 1) {
            rs += __shfl_xor_sync(0xffffffffu, rs, o);
            om  = fmaxf(om, __shfl_xor_sync(0xffffffffu, om, o));
        }
        if (lane == 0) { s_rowsum[c] = rs; s_q[c] = (pres && om < 0.6f) ? 1 : 0; }

        float x = (j < CC) ? s_M[3][c][j] : -3.4e38f;
        float m = x;
        #pragma unroll
        for (int o = 16; o > 0; o >>= 1) m = fmaxf(m, __shfl_xor_sync(0xffffffffu, m, o));
        float e = (j < CC) ? expf(x - m) : 0.f;
        float ssum = e;
        #pragma unroll
        for (int o = 16; o > 0; o >>= 1) ssum += __shfl_xor_sync(0xffffffffu, ssum, o);
        float tt = 0.f;
        if (j < CC) {
            float pr = e * (1.f / ssum);
            tt = (j == c) ? fmaxf(logf(pr), -100.f) : fmaxf(log1pf(-pr), -100.f);
        }
        #pragma unroll
        for (int o = 16; o > 0; o >>= 1) tt += __shfl_xor_sync(0xffffffffu, tt, o);
        if (lane == 0) s_term[c] = -tt * (1.f / (float)CC);
    }
    __syncthreads();

    // ---- T1: accumulate batch-0 losses; compose fc1 norms ----
    if (tid < CC) {
        int j = tid;
        float ss = s_q[j]
            ? 0.9025f*s_ns[2][j] + 0.095f*s_M[0][j][j] + 0.0025f*s_ns[0][j]
            : s_ns[2][j];
        s_invc1[j] = 1.f / fmaxf(sqrtf(ss), 1e-12f);
    }
    if (tid == 0) {
        float tot = 0.f;
        for (int c = 0; c < CC; c++) tot += s_rowsum[c];
        s_acc[0] -= tot * (1.f / (float)(CC*CC));
        float ls = 0.f; int n = 0;
        for (int c = 0; c < CC; c++) if (s_q[c]) { ls += s_term[c]; n++; }
        s_acc[1] += ls;
        if (n > 0) s_acc[1] /= (float)n;      // divides ACCUMULATED value, per reference
    }
    __syncthreads();

    // ---- T2: batch-1 epilogue with EMA-composed cos dots ----
    if (wid < CC) {
        int c = wid, j = lane;
        bool pres = __ldg(&label[CC + c]) > 0.5f;
        float v = 1e-5f;
        if (j < CC) {
            float raw = s_q[j] ? fmaf(0.95f, s_M[1][c][j], 0.05f*s_M[2][c][j])
                               : s_M[1][c][j];
            v = fabsf(raw * s_invf1[c] * s_invc1[j]);
            v = fminf(fmaxf(v, 1e-5f), 1.f - 1e-5f);
        }
        float lt = 0.f, ov = -1e30f;
        if (j < CC) {
            lt = (j == c) ? (pres ? logf(v) : log1pf(-v)) : log1pf(-v);
            ov = (j == c) ? -1e30f : v;
        }
        float rs = lt, om = ov;
        #pragma unroll
        for (int o = 16; o > 0; o >>= 1) {
            rs += __shfl_xor_sync(0xffffffffu, rs, o);
            om  = fmaxf(om, __shfl_xor_sync(0xffffffffu, om, o));
        }
        if (lane == 0) { s_rowsum[c] = rs; s_q1[c] = (pres && om < 0.6f) ? 1 : 0; }

        float x = (j < CC) ? s_M[4][c][j] : -3.4e38f;
        float m = x;
        #pragma unroll
        for (int o = 16; o > 0; o >>= 1) m = fmaxf(m, __shfl_xor_sync(0xffffffffu, m, o));
        float e = (j < CC) ? expf(x - m) : 0.f;
        float ssum = e;
        #pragma unroll
        for (int o = 16; o > 0; o >>= 1) ssum += __shfl_xor_sync(0xffffffffu, ssum, o);
        float tt = 0.f;
        if (j < CC) {
            float pr = e * (1.f / ssum);
            tt = (j == c) ? fmaxf(logf(pr), -100.f) : fmaxf(log1pf(-pr), -100.f);
        }
        #pragma unroll
        for (int o = 16; o > 0; o >>= 1) tt += __shfl_xor_sync(0xffffffffu, tt, o);
        if (lane == 0) s_term[c] = -tt * (1.f / (float)CC);
    }
    __syncthreads();

    if (tid == 0) {
        float tot = 0.f;
        for (int c = 0; c < CC; c++) tot += s_rowsum[c];
        s_acc[0] -= tot * (1.f / (float)(CC*CC));
        float ls = 0.f; int n = 0;
        for (int c = 0; c < CC; c++) if (s_q1[c]) { ls += s_term[c]; n++; }
        s_acc[1] += ls;
        if (n > 0) s_acc[1] /= (float)n;
        out[0] = s_acc[0] + s_acc[1];
    }

    // ---- cleanup epilogue: restore zero-scratch invariant for next launch ----
    {
        float4 z4 = make_float4(0.f, 0.f, 0.f, 0.f);
        float4* w4 = (float4*)g_W;
        for (int i = tid; i < (BB*CC*FHW)/4; i += 1024) w4[i] = z4;
        float4* f4 = (float4*)g_fsm;
        for (int i = tid; i < (BB*CC*DD)/4; i += 1024) f4[i] = z4;
        if (tid < BB*CC) { g_cnt[tid] = 0; g_done[tid] = 0; }
    }
}

extern "C" void kernel_launch(void* const* d_in, const int* in_sizes, int n_in,
                              void* d_out, int out_size)
{
    (void)in_sizes; (void)n_in; (void)out_size;
    const float* fmap  = (const float*)d_in[0];
    const float* cam   = (const float*)d_in[1];
    const float* label = (const float*)d_in[2];
    const float* proj  = (const float*)d_in[3];
    const float* fc0   = (const float*)d_in[4];
    const float* hig   = (const float*)d_in[5];
    const float* low   = (const float*)d_in[6];
    const float* bg    = (const float*)d_in[7];
    float* out = (float*)d_out;

    const int dynBytes = 3 * CC * PS * (int)sizeof(float);   // 62400
    cudaFuncSetAttribute(k_loss, cudaFuncAttributeMaxDynamicSharedMemorySize, dynBytes);

    k_pseudo    <<<BB*196, 256>>>(cam, label, hig, low, bg);
    k_topk_scan <<<BB*CC*NCH, 256>>>(cam, label);
    k_fsm       <<<BB*FH*2, 128>>>(fmap, label);
    k_loss      <<<1, 1024, dynBytes>>>(label, proj, fc0, out);
}

// round 11
// speedup vs baseline: 1.9053x; 1.6181x over previous
#include <cuda_runtime.h>

#define BB 2
#define CC 20
#define DD 256
#define WW 448
#define HWp 200704      // 448*448
#define FH 28
#define FW 28
#define FHW 784
#define KTOP 25
#define NCH 7           // pixel chunks for topk scan
#define CHPX 28672      // HWp / NCH

// ---- scratch (device globals). Invariant: zero at launch entry, re-zeroed by
// k_epi epilogue before launch exit. g_Wt/g_cv/g_ci/g_G/g_nrm are
// overwrite-before-read every launch and need no zero invariant.
static __device__ float g_W   [BB*CC*FHW];
static __device__ float g_Wt  [BB*CC*FHW];
static __device__ int   g_cnt [BB*CC];
static __device__ int   g_done[BB*CC];
static __device__ float g_fsm [BB*CC*DD];
static __device__ float g_cv  [BB*CC*NCH*KTOP];
static __device__ int   g_ci  [BB*CC*NCH*KTOP];
static __device__ float g_G   [60*40];   // G[t][s]: t in {fc0(0-19), f0(20-39), proj(40-59)}, s in {f0(0-19), f1(20-39)}
static __device__ float g_nrm [3*CC];    // sumsq rows: 0:f0, 1:f1, 2:fc0

// ---- pseudo-label + bilinear-weight scatter (fmax-only top-2 + rare rescan) ----
__global__ __launch_bounds__(256) void k_pseudo(
    const float* __restrict__ cam, const float* __restrict__ label,
    const float* __restrict__ hig, const float* __restrict__ low,
    const float* __restrict__ bg)
{
    __shared__ int   s_np;
    __shared__ int   s_list[CC];
    __shared__ float s_W[CC*3*30];   // [c][row 0..2][col 0..29] unclamped tile
    __shared__ int   s_cnt[CC];

    int tid = threadIdx.x;
    int b    = blockIdx.x / 196;
    int pblk = blockIdx.x % 196;
    int P0   = pblk * 1024;
    int p    = P0 + tid * 4;

    for (int i = tid; i < CC*90; i += 256) s_W[i] = 0.f;
    if (tid < CC) s_cnt[tid] = 0;
    if (tid < 32) {
        float lv = (tid < CC) ? __ldg(&label[b*CC + tid]) : 0.f;
        unsigned m = __ballot_sync(0xffffffffu, lv > 0.5f);
        if (tid < CC && lv > 0.5f) {
            int pos = __popc(m & ((1u << tid) - 1u));
            s_list[pos] = tid;
        }
        if (tid == 0) s_np = __popc(m);
    }
    __syncthreads();

    int np = s_np;
    const float* base = cam + (size_t)b * CC * HWp;

    float t1[4], t2[4];
    #pragma unroll
    for (int e = 0; e < 4; e++) { t1[e] = -1e30f; t2[e] = -1e30f; }

    for (int k = 0; k < np; k++) {
        int c = s_list[k];
        float4 v = __ldg((const float4*)(base + (size_t)c * HWp + p));
        float tm;
        tm = fminf(t1[0], v.x); t2[0] = fmaxf(t2[0], tm); t1[0] = fmaxf(t1[0], v.x);
        tm = fminf(t1[1], v.y); t2[1] = fmaxf(t2[1], tm); t1[1] = fmaxf(t1[1], v.y);
        tm = fminf(t1[2], v.z); t2[2] = fmaxf(t2[2], tm); t1[2] = fmaxf(t1[2], v.z);
        tm = fminf(t1[3], v.w); t2[3] = fmaxf(t2[3], tm); t1[3] = fmaxf(t1[3], v.w);
    }
    float Hh = __ldg(hig), Ll = __ldg(low), Gg = __ldg(bg);

    int Y0 = P0 / WW;
    int r0 = (int)floorf(((float)Y0 + 0.5f) * 0.0625f - 0.5f);

    #pragma unroll
    for (int e = 0; e < 4; e++) {
        float a = t1[e], s = t2[e];
        if (np < CC) { a = fmaxf(a, 0.f); s = fmaxf(s, 0.f); }  // absent classes are zeros
        bool lab = !(a < Hh) && !(a < Ll) && !(a < Gg) && !((a - s < 0.3f) && (a > Hh));
        lab = lab && (np > 0);
        if (lab) {
            int c = s_list[0];
            if (np > 1) {
                int pp0 = p + e;
                for (int k = 0; k < np; k++) {
                    int cc2 = s_list[k];
                    if (__ldg(&base[(size_t)cc2 * HWp + pp0]) == a) { c = cc2; break; }
                }
            }
            atomicAdd(&s_cnt[c], 1);
            int pp = p + e;
            int y = pp / WW, x = pp - y * WW;
            float sy = ((float)y + 0.5f) * 0.0625f - 0.5f;   // exact (dyadic)
            float sx = ((float)x + 0.5f) * 0.0625f - 0.5f;
            float y0f = floorf(sy), x0f = floorf(sx);
            float fy = sy - y0f,   fx = sx - x0f;
            int rr  = (int)y0f - r0;        // 0..1 (taps rr, rr+1 in [0,2])
            int c0  = (int)x0f + 1;         // 0..28
            float* tp = &s_W[c*90 + rr*30 + c0];
            atomicAdd(&tp[0],  (1.f-fy)*(1.f-fx));
            atomicAdd(&tp[1],  (1.f-fy)*fx);
            atomicAdd(&tp[30], fy*(1.f-fx));
            atomicAdd(&tp[31], fy*fx);
        }
    }
    __syncthreads();

    if (tid < CC && s_cnt[tid] > 0) atomicAdd(&g_cnt[b*CC + tid], s_cnt[tid]);
    for (int i = tid; i < CC*90; i += 256) {
        float v = s_W[i];
        if (v != 0.f) {
            int c = i / 90, rem = i - c*90;
            int rr = rem / 30, col = rem - rr*30;
            int gy = min(max(r0 + rr, 0), FH-1);
            int gx = min(max(col - 1, 0), FW-1);
            atomicAdd(&g_W[(b*CC + c)*FHW + gy*FW + gx], v);
        }
    }
}

// ---- top-25 chunk scan + fan-in merge: grid BB*CC*NCH, 256 thr ----
__global__ __launch_bounds__(256) void k_topk_scan(
    const float* __restrict__ cam, const float* __restrict__ label)
{
    int blk = blockIdx.x;
    int bc  = blk / NCH;
    int ch  = blk % NCH;
    int b = bc / CC, c = bc % CC;
    if (__ldg(&label[b*CC + c]) <= 0.5f) return;
    if (g_cnt[bc] != 0) return;

    int tid = threadIdx.x, wid = tid >> 5, lane = tid & 31;
    const float4* cp = (const float4*)(cam + ((size_t)b*CC + c) * HWp) + ch * (CHPX/4);

    float vals[KTOP]; int idxs[KTOP];   // ascending: vals[24] = max
    #pragma unroll
    for (int k = 0; k < KTOP; k++) { vals[k] = -1e30f; idxs[k] = 0x7fffffff; }
    float vmin = -1e30f;

    for (int it = 0; it < 28; it++) {
        int j = tid + it * 256;
        float4 v = __ldg(&cp[j]);
        int pbase = ch * CHPX + j * 4;
        float vv[4] = { v.x, v.y, v.z, v.w };
        #pragma unroll
        for (int e = 0; e < 4; e++) {
            float x = vv[e];
            if (x > vmin) {
                int k = 0;
                while (k < KTOP-1 && x > vals[k+1]) { vals[k] = vals[k+1]; idxs[k] = idxs[k+1]; k++; }
                vals[k] = x; idxs[k] = pbase + e;
                vmin = vals[0];
            }
        }
    }

    __shared__ float s_wv[8];
    __shared__ int   s_wi[8];
    __shared__ int   s_bi;
    int ptr = KTOP - 1;
    for (int r = 0; r < KTOP; r++) {
        float v  = (ptr >= 0) ? vals[ptr] : -1e30f;
        int   ii = (ptr >= 0) ? idxs[ptr] : 0x7fffffff;
        float mv = v; int mi = ii;
        #pragma unroll
        for (int off = 16; off > 0; off >>= 1) {
            float ov = __shfl_down_sync(0xffffffffu, mv, off);
            int   oi = __shfl_down_sync(0xffffffffu, mi, off);
            if (ov > mv || (ov == mv && oi < mi)) { mv = ov; mi = oi; }
        }
        if (lane == 0) { s_wv[wid] = mv; s_wi[wid] = mi; }
        __syncthreads();
        if (tid == 0) {
            float bv = s_wv[0]; int bi = s_wi[0];
            #pragma unroll
            for (int w = 1; w < 8; w++) {
                if (s_wv[w] > bv || (s_wv[w] == bv && s_wi[w] < bi)) { bv = s_wv[w]; bi = s_wi[w]; }
            }
            s_bi = bi;
            g_cv[blk*KTOP + r] = bv;
            g_ci[blk*KTOP + r] = bi;
        }
        __syncthreads();
        if (ptr >= 0 && idxs[ptr] == s_bi) ptr--;
    }

    // ---- fan-in: last chunk block merges the 7 lists and writes g_Wt[bc] ----
    __threadfence();
    __shared__ int s_last;
    if (tid == 0) s_last = (atomicAdd(&g_done[bc], 1) == NCH-1) ? 1 : 0;
    __syncthreads();
    if (!s_last) return;
    __threadfence();

    __shared__ float m_cv[NCH*KTOP];
    __shared__ int   m_ci[NCH*KTOP];
    __shared__ float s_wt[FHW];
    if (tid < NCH*KTOP) {
        m_cv[tid] = __ldcg(&g_cv[bc*NCH*KTOP + tid]);
        m_ci[tid] = __ldcg(&g_ci[bc*NCH*KTOP + tid]);
    }
    for (int i = tid; i < FHW; i += 256) s_wt[i] = 0.f;
    __syncthreads();

    if (tid < 32) {
        int ptr2 = 0;
        float v = -1e30f; int ii = 0x7fffffff;
        if (lane < NCH) { v = m_cv[lane*KTOP]; ii = m_ci[lane*KTOP]; }
        for (int r = 0; r < KTOP; r++) {
            float bv = v; int bi = ii;
            #pragma unroll
            for (int off = 4; off > 0; off >>= 1) {
                float ov = __shfl_xor_sync(0xffffffffu, bv, off);
                int   oi = __shfl_xor_sync(0xffffffffu, bi, off);
                if (ov > bv || (ov == bv && oi < bi)) { bv = ov; bi = oi; }
            }
            if (lane == 0) {
                int pp = bi;
                int y = pp / WW, x = pp - y * WW;
                float sy = ((float)y + 0.5f) * 0.0625f - 0.5f;
                float sx = ((float)x + 0.5f) * 0.0625f - 0.5f;
                float y0f = floorf(sy), x0f = floorf(sx);
                float fy = sy - y0f,   fx = sx - x0f;
                int y0 = (int)y0f, x0 = (int)x0f;
                int ya = min(max(y0, 0), FH-1),   yb = min(max(y0+1, 0), FH-1);
                int xa = min(max(x0, 0), FW-1),   xb = min(max(x0+1, 0), FW-1);
                s_wt[ya*FW + xa] += (1.f-fy)*(1.f-fx);
                s_wt[ya*FW + xb] += (1.f-fy)*fx;
                s_wt[yb*FW + xa] += fy*(1.f-fx);
                s_wt[yb*FW + xb] += fy*fx;
            }
            if (lane < NCH && ii == bi) {
                ptr2++;
                if (ptr2 < KTOP) { v = m_cv[lane*KTOP + ptr2]; ii = m_ci[lane*KTOP + ptr2]; }
                else             { v = -1e30f; ii = 0x7fffffff; }
            }
        }
    }
    __syncthreads();
    for (int i = tid; i < FHW; i += 256) g_Wt[bc*FHW + i] = s_wt[i];
}

// ---- fsm: grid = BB*28rows*2halves = 112 blocks, 128 thr ----
__global__ __launch_bounds__(128) void k_fsm(
    const float* __restrict__ fmap, const float* __restrict__ label)
{
    __shared__ int    s_np, s_nact;
    __shared__ int    s_list[CC];
    __shared__ int    s_act[CC];
    __shared__ int    s_nz[CC];
    __shared__ int    s_cnti[CC];
    __shared__ float  s_inv[CC];
    __shared__ float4 s_cw[CC][7];

    int tid  = threadIdx.x;
    int half = blockIdx.x & 1;
    int row  = (blockIdx.x >> 1) % FH;
    int b    = blockIdx.x / (2*FH);

    int d = half*128 + tid;
    const float4* fr = (const float4*)(fmap + ((size_t)(b*DD + d)) * FHW + row*FW);
    float4 f[7];
    #pragma unroll
    for (int i = 0; i < 7; i++) f[i] = __ldg(&fr[i]);

    if (tid < 32) {
        float lv = (tid < CC) ? __ldg(&label[b*CC + tid]) : 0.f;
        unsigned m = __ballot_sync(0xffffffffu, lv > 0.5f);
        if (tid < CC && lv > 0.5f) s_list[__popc(m & ((1u << tid) - 1u))] = tid;
        if (tid == 0) s_np = __popc(m);
    }
    if (tid < CC) s_nz[tid] = 0;
    __syncthreads();
    int np = s_np;

    if (tid < np) {
        int bc = b*CC + s_list[tid];
        int cnt = g_cnt[bc];
        s_cnti[tid] = cnt;
        s_inv[tid]  = (cnt > 0) ? (1.f / (float)cnt) : 0.04f;
    }
    __syncthreads();

    for (int idx = tid; idx < np*7; idx += 128) {
        int k = idx / 7, q = idx - k*7;
        int bc = b*CC + s_list[k];
        const float4* src = (s_cnti[k] > 0)
            ? (const float4*)(g_W  + bc*FHW + row*FW)
            : (const float4*)(g_Wt + bc*FHW + row*FW);
        float4 v = src[q];
        float inv = s_inv[k];
        v.x *= inv; v.y *= inv; v.z *= inv; v.w *= inv;
        s_cw[k][q] = v;
        if (v.x != 0.f || v.y != 0.f || v.z != 0.f || v.w != 0.f) s_nz[k] = 1;
    }
    __syncthreads();

    if (tid < 32) {
        bool a = (tid < np) && s_nz[tid];
        unsigned m = __ballot_sync(0xffffffffu, a);
        if (a) s_act[__popc(m & ((1u << tid) - 1u))] = tid;
        if (tid == 0) s_nact = __popc(m);
    }
    __syncthreads();
    int nact = s_nact;
    if (nact == 0) return;

    for (int a = 0; a < nact; a++) {
        int k = s_act[a];
        int c = s_list[k];
        float a0 = 0.f, a1 = 0.f, a2 = 0.f, a3 = 0.f;
        #pragma unroll
        for (int i = 0; i < 7; i++) {
            float4 w = s_cw[k][i];
            a0 = fmaf(f[i].x, w.x, a0);
            a1 = fmaf(f[i].y, w.y, a1);
            a2 = fmaf(f[i].z, w.z, a2);
            a3 = fmaf(f[i].w, w.w, a3);
        }
        atomicAdd(&g_fsm[(b*CC + c)*DD + d], (a0 + a1) + (a2 + a3));
    }
}

// ---- dots: grid 120 blocks. Blocks 0-59: G[t][0..39] (target row in regs,
//      8 warps x 5 sources). Blocks 60-119: row sumsq norms. ----
__global__ __launch_bounds__(256) void k_dots(
    const float* __restrict__ fc0, const float* __restrict__ proj)
{
    int t = blockIdx.x;
    int lane = threadIdx.x & 31, wid = threadIdx.x >> 5;

    if (t < 60) {
        int type = t / 20, row = t % 20;
        const float* tp = (type == 0) ? (fc0 + row*DD)
                        : (type == 1) ? (g_fsm + row*DD)
                                      : (proj + row*DD);
        const float4* t4 = (const float4*)tp;
        float4 ta = __ldg(&t4[lane*2]);
        float4 tb = __ldg(&t4[lane*2 + 1]);
        #pragma unroll
        for (int i = 0; i < 5; i++) {
            int s = wid*5 + i;
            const float4* s4 = (const float4*)(g_fsm + s*DD);
            float4 sa = __ldg(&s4[lane*2]);
            float4 sb = __ldg(&s4[lane*2 + 1]);
            float d = sa.x*ta.x + sa.y*ta.y + sa.z*ta.z + sa.w*ta.w
                    + sb.x*tb.x + sb.y*tb.y + sb.z*tb.z + sb.w*tb.w;
            #pragma unroll
            for (int o = 16; o > 0; o >>= 1) d += __shfl_xor_sync(0xffffffffu, d, o);
            if (lane == 0) g_G[t*40 + s] = d;
        }
    } else {
        if (wid != 0) return;
        int idx = t - 60, grp = idx / 20, row = idx % 20;
        const float* rp = (grp == 0) ? (g_fsm + row*DD)
                        : (grp == 1) ? (g_fsm + (CC + row)*DD)
                                     : (fc0 + row*DD);
        const float4* r4 = (const float4*)rp;
        float4 u = __ldg(&r4[lane*2]);
        float4 w = __ldg(&r4[lane*2 + 1]);
        float ss = u.x*u.x + u.y*u.y + u.z*u.z + u.w*u.w
                 + w.x*w.x + w.y*w.y + w.z*w.z + w.w*w.w;
        #pragma unroll
        for (int o = 16; o > 0; o >>= 1) ss += __shfl_xor_sync(0xffffffffu, ss, o);
        if (lane == 0) g_nrm[grp*CC + row] = ss;
    }
}

// ---- epilogue: scalar loss from G + norms, 1 block 640 thr, + cleanup ----
// G mapping (t-major, stride 41 in shared): M0[c][j]=G[j][c]  M1[c][j]=G[j][20+c]
// M2[c][j]=G[20+j][20+c]  M3[c][j]=G[40+j][c]  M4[c][j]=G[40+j][20+c]
__global__ __launch_bounds__(640) void k_epi(
    const float* __restrict__ label, float* __restrict__ out)
{
    __shared__ float s_G[60*41];
    __shared__ float s_n[3][CC];
    __shared__ float s_invf0[CC], s_invf1[CC], s_invc0[CC], s_invc1[CC];
    __shared__ float s_rowsum[CC], s_term[CC];
    __shared__ int   s_q[CC], s_q1[CC];
    __shared__ float s_acc[2];

    int tid = threadIdx.x, wid = tid >> 5, lane = tid & 31;

    for (int i = tid; i < 60*40; i += 640) {
        int t = i / 40, s = i - t*40;
        s_G[t*41 + s] = g_G[i];
    }
    if (tid < 60) s_n[tid/CC][tid%CC] = g_nrm[tid];
    if (tid == 0) { s_acc[0] = 0.f; s_acc[1] = 0.f; }
    __syncthreads();

    if (tid < CC) {
        s_invf0[tid] = 1.f / fmaxf(sqrtf(s_n[0][tid]), 1e-12f);
        s_invf1[tid] = 1.f / fmaxf(sqrtf(s_n[1][tid]), 1e-12f);
        s_invc0[tid] = 1.f / fmaxf(sqrtf(s_n[2][tid]), 1e-12f);
    }
    __syncthreads();

    // ---- T0: batch-0 epilogue (warp c, lane j) ----
    if (wid < CC) {
        int c = wid, j = lane;
        bool pres = __ldg(&label[c]) > 0.5f;
        float v = 1e-5f;
        if (j < CC) {
            v = fabsf(s_G[j*41 + c] * s_invf0[c] * s_invc0[j]);
            v = fminf(fmaxf(v, 1e-5f), 1.f - 1e-5f);
        }
        float lt = 0.f, ov = -1e30f;
        if (j < CC) {
            lt = (j == c) ? (pres ? logf(v) : log1pf(-v)) : log1pf(-v);
            ov = (j == c) ? -1e30f : v;
        }
        float rs = lt, om = ov;
        #pragma unroll
        for (int o = 16; o > 0; o >>= 1) {
            rs += __shfl_xor_sync(0xffffffffu, rs, o);
            om  = fmaxf(om, __shfl_xor_sync(0xffffffffu, om, o));
        }
        if (lane == 0) { s_rowsum[c] = rs; s_q[c] = (pres && om < 0.6f) ? 1 : 0; }

        float x = (j < CC) ? s_G[(40+j)*41 + c] : -3.4e38f;
        float m = x;
        #pragma unroll
        for (int o = 16; o > 0; o >>= 1) m = fmaxf(m, __shfl_xor_sync(0xffffffffu, m, o));
        float e = (j < CC) ? expf(x - m) : 0.f;
        float ssum = e;
        #pragma unroll
        for (int o = 16; o > 0; o >>= 1) ssum += __shfl_xor_sync(0xffffffffu, ssum, o);
        float tt = 0.f;
        if (j < CC) {
            float pr = e * (1.f / ssum);
            tt = (j == c) ? fmaxf(logf(pr), -100.f) : fmaxf(log1pf(-pr), -100.f);
        }
        #pragma unroll
        for (int o = 16; o > 0; o >>= 1) tt += __shfl_xor_sync(0xffffffffu, tt, o);
        if (lane == 0) s_term[c] = -tt * (1.f / (float)CC);
    }
    __syncthreads();

    // ---- T1: accumulate batch-0 losses; compose fc1 norms ----
    if (tid < CC) {
        int j = tid;
        float ss = s_q[j]
            ? 0.9025f*s_n[2][j] + 0.095f*s_G[j*41 + j] + 0.0025f*s_n[0][j]
            : s_n[2][j];
        s_invc1[j] = 1.f / fmaxf(sqrtf(ss), 1e-12f);
    }
    if (tid == 0) {
        float tot = 0.f;
        for (int c = 0; c < CC; c++) tot += s_rowsum[c];
        s_acc[0] -= tot * (1.f / (float)(CC*CC));
        float ls = 0.f; int n = 0;
        for (int c = 0; c < CC; c++) if (s_q[c]) { ls += s_term[c]; n++; }
        s_acc[1] += ls;
        if (n > 0) s_acc[1] /= (float)n;      // divides ACCUMULATED value, per reference
    }
    __syncthreads();

    // ---- T2: batch-1 epilogue with EMA-composed cos dots ----
    if (wid < CC) {
        int c = wid, j = lane;
        bool pres = __ldg(&label[CC + c]) > 0.5f;
        float v = 1e-5f;
        if (j < CC) {
            float m1 = s_G[j*41 + 20 + c];
            float raw = s_q[j] ? fmaf(0.95f, m1, 0.05f * s_G[(20+j)*41 + 20 + c]) : m1;
            v = fabsf(raw * s_invf1[c] * s_invc1[j]);
            v = fminf(fmaxf(v, 1e-5f), 1.f - 1e-5f);
        }
        float lt = 0.f, ov = -1e30f;
        if (j < CC) {
            lt = (j == c) ? (pres ? logf(v) : log1pf(-v)) : log1pf(-v);
            ov = (j == c) ? -1e30f : v;
        }
        float rs = lt, om = ov;
        #pragma unroll
        for (int o = 16; o > 0; o >>= 1) {
            rs += __shfl_xor_sync(0xffffffffu, rs, o);
            om  = fmaxf(om, __shfl_xor_sync(0xffffffffu, om, o));
        }
        if (lane == 0) { s_rowsum[c] = rs; s_q1[c] = (pres && om < 0.6f) ? 1 : 0; }

        float x = (j < CC) ? s_G[(40+j)*41 + 20 + c] : -3.4e38f;
        float m = x;
        #pragma unroll
        for (int o = 16; o > 0; o >>= 1) m = fmaxf(m, __shfl_xor_sync(0xffffffffu, m, o));
        float e = (j < CC) ? expf(x - m) : 0.f;
        float ssum = e;
        #pragma unroll
        for (int o = 16; o > 0; o >>= 1) ssum += __shfl_xor_sync(0xffffffffu, ssum, o);
        float tt = 0.f;
        if (j < CC) {
            float pr = e * (1.f / ssum);
            tt = (j == c) ? fmaxf(logf(pr), -100.f) : fmaxf(log1pf(-pr), -100.f);
        }
        #pragma unroll
        for (int o = 16; o > 0; o >>= 1) tt += __shfl_xor_sync(0xffffffffu, tt, o);
        if (lane == 0) s_term[c] = -tt * (1.f / (float)CC);
    }
    __syncthreads();

    if (tid == 0) {
        float tot = 0.f;
        for (int c = 0; c < CC; c++) tot += s_rowsum[c];
        s_acc[0] -= tot * (1.f / (float)(CC*CC));
        float ls = 0.f; int n = 0;
        for (int c = 0; c < CC; c++) if (s_q1[c]) { ls += s_term[c]; n++; }
        s_acc[1] += ls;
        if (n > 0) s_acc[1] /= (float)n;
        out[0] = s_acc[0] + s_acc[1];
    }

    // ---- cleanup epilogue: restore zero-scratch invariant for next launch ----
    {
        float4 z4 = make_float4(0.f, 0.f, 0.f, 0.f);
        float4* w4 = (float4*)g_W;
        for (int i = tid; i < (BB*CC*FHW)/4; i += 640) w4[i] = z4;
        float4* f4 = (float4*)g_fsm;
        for (int i = tid; i < (BB*CC*DD)/4; i += 640) f4[i] = z4;
        if (tid < BB*CC) { g_cnt[tid] = 0; g_done[tid] = 0; }
    }
}

extern "C" void kernel_launch(void* const* d_in, const int* in_sizes, int n_in,
                              void* d_out, int out_size)
{
    (void)in_sizes; (void)n_in; (void)out_size;
    const float* fmap  = (const float*)d_in[0];
    const float* cam   = (const float*)d_in[1];
    const float* label = (const float*)d_in[2];
    const float* proj  = (const float*)d_in[3];
    const float* fc0   = (const float*)d_in[4];
    const float* hig   = (const float*)d_in[5];
    const float* low   = (const float*)d_in[6];
    const float* bg    = (const float*)d_in[7];
    float* out = (float*)d_out;

    k_pseudo    <<<BB*196, 256>>>(cam, label, hig, low, bg);
    k_topk_scan <<<BB*CC*NCH, 256>>>(cam, label);
    k_fsm       <<<BB*FH*2, 128>>>(fmap, label);
    k_dots      <<<120, 256>>>(fc0, proj);
    k_epi       <<<1, 640>>>(label, out);
}

// round 12
// speedup vs baseline: 2.0600x; 1.0812x over previous
#include <cuda_runtime.h>

#define BB 2
#define CC 20
#define DD 256
#define WW 448
#define HWp 200704      // 448*448
#define FH 28
#define FW 28
#define FHW 784
#define KTOP 25
#define NCH 7           // pixel chunks for topk scan
#define CHPX 28672      // HWp / NCH

// ---- scratch (device globals). Invariant: zero at launch entry, re-zeroed by
// the k_loss2 fan-in epilogue before launch exit. g_Wt/g_cv/g_ci/g_G/g_nrm are
// overwrite-before-read every launch and need no zero invariant.
static __device__ float g_W   [BB*CC*FHW];
static __device__ float g_Wt  [BB*CC*FHW];
static __device__ int   g_cnt [BB*CC];
static __device__ int   g_done[BB*CC];
static __device__ int   g_sync;          // fan-in counter for k_loss2
static __device__ float g_fsm [BB*CC*DD];
static __device__ float g_cv  [BB*CC*NCH*KTOP];
static __device__ int   g_ci  [BB*CC*NCH*KTOP];
static __device__ float g_G   [60*40];   // G[t][s]: t in {fc0(0-19), f0(20-39), proj(40-59)}, s in {f0(0-19), f1(20-39)}
static __device__ float g_nrm [3*CC];    // sumsq rows: 0:f0, 1:f1, 2:fc0

// ---- pseudo-label + bilinear-weight scatter (fmax-only top-2 + rare rescan) ----
__global__ __launch_bounds__(256) void k_pseudo(
    const float* __restrict__ cam, const float* __restrict__ label,
    const float* __restrict__ hig, const float* __restrict__ low,
    const float* __restrict__ bg)
{
    __shared__ int   s_np;
    __shared__ int   s_list[CC];
    __shared__ float s_W[CC*3*30];   // [c][row 0..2][col 0..29] unclamped tile
    __shared__ int   s_cnt[CC];

    int tid = threadIdx.x;
    int b    = blockIdx.x / 196;
    int pblk = blockIdx.x % 196;
    int P0   = pblk * 1024;
    int p    = P0 + tid * 4;

    for (int i = tid; i < CC*90; i += 256) s_W[i] = 0.f;
    if (tid < CC) s_cnt[tid] = 0;
    if (tid < 32) {
        float lv = (tid < CC) ? __ldg(&label[b*CC + tid]) : 0.f;
        unsigned m = __ballot_sync(0xffffffffu, lv > 0.5f);
        if (tid < CC && lv > 0.5f) {
            int pos = __popc(m & ((1u << tid) - 1u));
            s_list[pos] = tid;
        }
        if (tid == 0) s_np = __popc(m);
    }
    __syncthreads();

    int np = s_np;
    const float* base = cam + (size_t)b * CC * HWp;

    float t1[4], t2[4];
    #pragma unroll
    for (int e = 0; e < 4; e++) { t1[e] = -1e30f; t2[e] = -1e30f; }

    for (int k = 0; k < np; k++) {
        int c = s_list[k];
        float4 v = __ldg((const float4*)(base + (size_t)c * HWp + p));
        float tm;
        tm = fminf(t1[0], v.x); t2[0] = fmaxf(t2[0], tm); t1[0] = fmaxf(t1[0], v.x);
        tm = fminf(t1[1], v.y); t2[1] = fmaxf(t2[1], tm); t1[1] = fmaxf(t1[1], v.y);
        tm = fminf(t1[2], v.z); t2[2] = fmaxf(t2[2], tm); t1[2] = fmaxf(t1[2], v.z);
        tm = fminf(t1[3], v.w); t2[3] = fmaxf(t2[3], tm); t1[3] = fmaxf(t1[3], v.w);
    }
    float Hh = __ldg(hig), Ll = __ldg(low), Gg = __ldg(bg);

    int Y0 = P0 / WW;
    int r0 = (int)floorf(((float)Y0 + 0.5f) * 0.0625f - 0.5f);

    #pragma unroll
    for (int e = 0; e < 4; e++) {
        float a = t1[e], s = t2[e];
        if (np < CC) { a = fmaxf(a, 0.f); s = fmaxf(s, 0.f); }  // absent classes are zeros
        bool lab = !(a < Hh) && !(a < Ll) && !(a < Gg) && !((a - s < 0.3f) && (a > Hh));
        lab = lab && (np > 0);
        if (lab) {
            int c = s_list[0];
            if (np > 1) {
                int pp0 = p + e;
                for (int k = 0; k < np; k++) {
                    int cc2 = s_list[k];
                    if (__ldg(&base[(size_t)cc2 * HWp + pp0]) == a) { c = cc2; break; }
                }
            }
            atomicAdd(&s_cnt[c], 1);
            int pp = p + e;
            int y = pp / WW, x = pp - y * WW;
            float sy = ((float)y + 0.5f) * 0.0625f - 0.5f;   // exact (dyadic)
            float sx = ((float)x + 0.5f) * 0.0625f - 0.5f;
            float y0f = floorf(sy), x0f = floorf(sx);
            float fy = sy - y0f,   fx = sx - x0f;
            int rr  = (int)y0f - r0;        // 0..1 (taps rr, rr+1 in [0,2])
            int c0  = (int)x0f + 1;         // 0..28
            float* tp = &s_W[c*90 + rr*30 + c0];
            atomicAdd(&tp[0],  (1.f-fy)*(1.f-fx));
            atomicAdd(&tp[1],  (1.f-fy)*fx);
            atomicAdd(&tp[30], fy*(1.f-fx));
            atomicAdd(&tp[31], fy*fx);
        }
    }
    __syncthreads();

    if (tid < CC && s_cnt[tid] > 0) atomicAdd(&g_cnt[b*CC + tid], s_cnt[tid]);
    for (int i = tid; i < CC*90; i += 256) {
        float v = s_W[i];
        if (v != 0.f) {
            int c = i / 90, rem = i - c*90;
            int rr = rem / 30, col = rem - rr*30;
            int gy = min(max(r0 + rr, 0), FH-1);
            int gx = min(max(col - 1, 0), FW-1);
            atomicAdd(&g_W[(b*CC + c)*FHW + gy*FW + gx], v);
        }
    }
}

// ---- top-25 chunk scan + fan-in merge: grid BB*CC*NCH, 256 thr ----
__global__ __launch_bounds__(256) void k_topk_scan(
    const float* __restrict__ cam, const float* __restrict__ label)
{
    int blk = blockIdx.x;
    int bc  = blk / NCH;
    int ch  = blk % NCH;
    int b = bc / CC, c = bc % CC;
    if (__ldg(&label[b*CC + c]) <= 0.5f) return;
    if (g_cnt[bc] != 0) return;

    int tid = threadIdx.x, wid = tid >> 5, lane = tid & 31;
    const float4* cp = (const float4*)(cam + ((size_t)b*CC + c) * HWp) + ch * (CHPX/4);

    float vals[KTOP]; int idxs[KTOP];   // ascending: vals[24] = max
    #pragma unroll
    for (int k = 0; k < KTOP; k++) { vals[k] = -1e30f; idxs[k] = 0x7fffffff; }
    float vmin = -1e30f;

    for (int it = 0; it < 28; it++) {
        int j = tid + it * 256;
        float4 v = __ldg(&cp[j]);
        int pbase = ch * CHPX + j * 4;
        float vv[4] = { v.x, v.y, v.z, v.w };
        #pragma unroll
        for (int e = 0; e < 4; e++) {
            float x = vv[e];
            if (x > vmin) {
                int k = 0;
                while (k < KTOP-1 && x > vals[k+1]) { vals[k] = vals[k+1]; idxs[k] = idxs[k+1]; k++; }
                vals[k] = x; idxs[k] = pbase + e;
                vmin = vals[0];
            }
        }
    }

    __shared__ float s_wv[8];
    __shared__ int   s_wi[8];
    __shared__ int   s_bi;
    int ptr = KTOP - 1;
    for (int r = 0; r < KTOP; r++) {
        float v  = (ptr >= 0) ? vals[ptr] : -1e30f;
        int   ii = (ptr >= 0) ? idxs[ptr] : 0x7fffffff;
        float mv = v; int mi = ii;
        #pragma unroll
        for (int off = 16; off > 0; off >>= 1) {
            float ov = __shfl_down_sync(0xffffffffu, mv, off);
            int   oi = __shfl_down_sync(0xffffffffu, mi, off);
            if (ov > mv || (ov == mv && oi < mi)) { mv = ov; mi = oi; }
        }
        if (lane == 0) { s_wv[wid] = mv; s_wi[wid] = mi; }
        __syncthreads();
        if (tid == 0) {
            float bv = s_wv[0]; int bi = s_wi[0];
            #pragma unroll
            for (int w = 1; w < 8; w++) {
                if (s_wv[w] > bv || (s_wv[w] == bv && s_wi[w] < bi)) { bv = s_wv[w]; bi = s_wi[w]; }
            }
            s_bi = bi;
            g_cv[blk*KTOP + r] = bv;
            g_ci[blk*KTOP + r] = bi;
        }
        __syncthreads();
        if (ptr >= 0 && idxs[ptr] == s_bi) ptr--;
    }

    // ---- fan-in: last chunk block merges the 7 lists and writes g_Wt[bc] ----
    __threadfence();
    __shared__ int s_last;
    if (tid == 0) s_last = (atomicAdd(&g_done[bc], 1) == NCH-1) ? 1 : 0;
    __syncthreads();
    if (!s_last) return;
    __threadfence();

    __shared__ float m_cv[NCH*KTOP];
    __shared__ int   m_ci[NCH*KTOP];
    __shared__ float s_wt[FHW];
    if (tid < NCH*KTOP) {
        m_cv[tid] = __ldcg(&g_cv[bc*NCH*KTOP + tid]);
        m_ci[tid] = __ldcg(&g_ci[bc*NCH*KTOP + tid]);
    }
    for (int i = tid; i < FHW; i += 256) s_wt[i] = 0.f;
    __syncthreads();

    if (tid < 32) {
        int ptr2 = 0;
        float v = -1e30f; int ii = 0x7fffffff;
        if (lane < NCH) { v = m_cv[lane*KTOP]; ii = m_ci[lane*KTOP]; }
        for (int r = 0; r < KTOP; r++) {
            float bv = v; int bi = ii;
            #pragma unroll
            for (int off = 4; off > 0; off >>= 1) {
                float ov = __shfl_xor_sync(0xffffffffu, bv, off);
                int   oi = __shfl_xor_sync(0xffffffffu, bi, off);
                if (ov > bv || (ov == bv && oi < bi)) { bv = ov; bi = oi; }
            }
            if (lane == 0) {
                int pp = bi;
                int y = pp / WW, x = pp - y * WW;
                float sy = ((float)y + 0.5f) * 0.0625f - 0.5f;
                float sx = ((float)x + 0.5f) * 0.0625f - 0.5f;
                float y0f = floorf(sy), x0f = floorf(sx);
                float fy = sy - y0f,   fx = sx - x0f;
                int y0 = (int)y0f, x0 = (int)x0f;
                int ya = min(max(y0, 0), FH-1),   yb = min(max(y0+1, 0), FH-1);
                int xa = min(max(x0, 0), FW-1),   xb = min(max(x0+1, 0), FW-1);
                s_wt[ya*FW + xa] += (1.f-fy)*(1.f-fx);
                s_wt[ya*FW + xb] += (1.f-fy)*fx;
                s_wt[yb*FW + xa] += fy*(1.f-fx);
                s_wt[yb*FW + xb] += fy*fx;
            }
            if (lane < NCH && ii == bi) {
                ptr2++;
                if (ptr2 < KTOP) { v = m_cv[lane*KTOP + ptr2]; ii = m_ci[lane*KTOP + ptr2]; }
                else             { v = -1e30f; ii = 0x7fffffff; }
            }
        }
    }
    __syncthreads();
    for (int i = tid; i < FHW; i += 256) g_Wt[bc*FHW + i] = s_wt[i];
}

// ---- fsm: grid = BB*28rows*2halves = 112 blocks, 128 thr ----
__global__ __launch_bounds__(128) void k_fsm(
    const float* __restrict__ fmap, const float* __restrict__ label)
{
    __shared__ int    s_np, s_nact;
    __shared__ int    s_list[CC];
    __shared__ int    s_act[CC];
    __shared__ int    s_nz[CC];
    __shared__ int    s_cnti[CC];
    __shared__ float  s_inv[CC];
    __shared__ float4 s_cw[CC][7];

    int tid  = threadIdx.x;
    int half = blockIdx.x & 1;
    int row  = (blockIdx.x >> 1) % FH;
    int b    = blockIdx.x / (2*FH);

    int d = half*128 + tid;
    const float4* fr = (const float4*)(fmap + ((size_t)(b*DD + d)) * FHW + row*FW);
    float4 f[7];
    #pragma unroll
    for (int i = 0; i < 7; i++) f[i] = __ldg(&fr[i]);

    if (tid < 32) {
        float lv = (tid < CC) ? __ldg(&label[b*CC + tid]) : 0.f;
        unsigned m = __ballot_sync(0xffffffffu, lv > 0.5f);
        if (tid < CC && lv > 0.5f) s_list[__popc(m & ((1u << tid) - 1u))] = tid;
        if (tid == 0) s_np = __popc(m);
    }
    if (tid < CC) s_nz[tid] = 0;
    __syncthreads();
    int np = s_np;

    if (tid < np) {
        int bc = b*CC + s_list[tid];
        int cnt = g_cnt[bc];
        s_cnti[tid] = cnt;
        s_inv[tid]  = (cnt > 0) ? (1.f / (float)cnt) : 0.04f;
    }
    __syncthreads();

    for (int idx = tid; idx < np*7; idx += 128) {
        int k = idx / 7, q = idx - k*7;
        int bc = b*CC + s_list[k];
        const float4* src = (s_cnti[k] > 0)
            ? (const float4*)(g_W  + bc*FHW + row*FW)
            : (const float4*)(g_Wt + bc*FHW + row*FW);
        float4 v = src[q];
        float inv = s_inv[k];
        v.x *= inv; v.y *= inv; v.z *= inv; v.w *= inv;
        s_cw[k][q] = v;
        if (v.x != 0.f || v.y != 0.f || v.z != 0.f || v.w != 0.f) s_nz[k] = 1;
    }
    __syncthreads();

    if (tid < 32) {
        bool a = (tid < np) && s_nz[tid];
        unsigned m = __ballot_sync(0xffffffffu, a);
        if (a) s_act[__popc(m & ((1u << tid) - 1u))] = tid;
        if (tid == 0) s_nact = __popc(m);
    }
    __syncthreads();
    int nact = s_nact;
    if (nact == 0) return;

    for (int a = 0; a < nact; a++) {
        int k = s_act[a];
        int c = s_list[k];
        float a0 = 0.f, a1 = 0.f, a2 = 0.f, a3 = 0.f;
        #pragma unroll
        for (int i = 0; i < 7; i++) {
            float4 w = s_cw[k][i];
            a0 = fmaf(f[i].x, w.x, a0);
            a1 = fmaf(f[i].y, w.y, a1);
            a2 = fmaf(f[i].z, w.z, a2);
            a3 = fmaf(f[i].w, w.w, a3);
        }
        atomicAdd(&g_fsm[(b*CC + c)*DD + d], (a0 + a1) + (a2 + a3));
    }
}

// ---- fused loss: grid 120 x 640. Blocks 0-59: 40 G-dots each (20 warps x 2
//      sources). Blocks 60-119: row norms. Last-arriving block runs the full
//      scalar epilogue + scratch cleanup (fan-in, deadlock-free). ----
// G mapping (t-major, stride 41 in shared): M0[c][j]=G[j][c]  M1[c][j]=G[j][20+c]
// M2[c][j]=G[20+j][20+c]  M3[c][j]=G[40+j][c]  M4[c][j]=G[40+j][20+c]
__global__ __launch_bounds__(640) void k_loss2(
    const float* __restrict__ label, const float* __restrict__ fc0,
    const float* __restrict__ proj, float* __restrict__ out)
{
    int t = blockIdx.x;
    int tid = threadIdx.x, wid = tid >> 5, lane = tid & 31;

    if (t < 60) {
        int type = t / 20, row = t % 20;
        const float* tp = (type == 0) ? (fc0 + row*DD)
                        : (type == 1) ? (g_fsm + row*DD)
                                      : (proj + row*DD);
        const float4* t4 = (const float4*)tp;
        float4 ta = __ldg(&t4[lane*2]);
        float4 tb = __ldg(&t4[lane*2 + 1]);
        #pragma unroll
        for (int i = 0; i < 2; i++) {
            int s = wid*2 + i;
            const float4* s4 = (const float4*)(g_fsm + s*DD);
            float4 sa = __ldg(&s4[lane*2]);
            float4 sb = __ldg(&s4[lane*2 + 1]);
            float d = sa.x*ta.x + sa.y*ta.y + sa.z*ta.z + sa.w*ta.w
                    + sb.x*tb.x + sb.y*tb.y + sb.z*tb.z + sb.w*tb.w;
            #pragma unroll
            for (int o = 16; o > 0; o >>= 1) d += __shfl_xor_sync(0xffffffffu, d, o);
            if (lane == 0) g_G[t*40 + s] = d;
        }
    } else if (wid == 0) {
        int idx = t - 60, grp = idx / 20, row = idx % 20;
        const float* rp = (grp == 0) ? (g_fsm + row*DD)
                        : (grp == 1) ? (g_fsm + (CC + row)*DD)
                                     : (fc0 + row*DD);
        const float4* r4 = (const float4*)rp;
        float4 u = __ldg(&r4[lane*2]);
        float4 w = __ldg(&r4[lane*2 + 1]);
        float ss = u.x*u.x + u.y*u.y + u.z*u.z + u.w*u.w
                 + w.x*w.x + w.y*w.y + w.z*w.z + w.w*w.w;
        #pragma unroll
        for (int o = 16; o > 0; o >>= 1) ss += __shfl_xor_sync(0xffffffffu, ss, o);
        if (lane == 0) g_nrm[grp*CC + row] = ss;
    }

    // ---- fan-in: last block to arrive runs the epilogue ----
    __threadfence();
    __shared__ int s_last;
    if (tid == 0) s_last = (atomicAdd(&g_sync, 1) == 119) ? 1 : 0;
    __syncthreads();
    if (!s_last) return;
    __threadfence();

    __shared__ float s_G[60*41];
    __shared__ float s_n[3][CC];
    __shared__ float s_invf0[CC], s_invf1[CC], s_invc0[CC], s_invc1[CC];
    __shared__ float s_rowsum[CC], s_term[CC];
    __shared__ int   s_q[CC], s_q1[CC];
    __shared__ float s_acc[2];

    for (int i = tid; i < 60*40; i += 640) {
        int tt2 = i / 40, s = i - tt2*40;
        s_G[tt2*41 + s] = __ldcg(&g_G[i]);
    }
    if (tid < 60) s_n[tid/CC][tid%CC] = __ldcg(&g_nrm[tid]);
    if (tid == 0) { s_acc[0] = 0.f; s_acc[1] = 0.f; }
    __syncthreads();

    if (tid < CC) {
        s_invf0[tid] = 1.f / fmaxf(sqrtf(s_n[0][tid]), 1e-12f);
        s_invf1[tid] = 1.f / fmaxf(sqrtf(s_n[1][tid]), 1e-12f);
        s_invc0[tid] = 1.f / fmaxf(sqrtf(s_n[2][tid]), 1e-12f);
    }
    __syncthreads();

    // ---- T0: batch-0 epilogue (warp c, lane j) ----
    if (wid < CC) {
        int c = wid, j = lane;
        bool pres = __ldg(&label[c]) > 0.5f;
        float v = 1e-5f;
        if (j < CC) {
            v = fabsf(s_G[j*41 + c] * s_invf0[c] * s_invc0[j]);
            v = fminf(fmaxf(v, 1e-5f), 1.f - 1e-5f);
        }
        float lt = 0.f, ov = -1e30f;
        if (j < CC) {
            lt = (j == c) ? (pres ? logf(v) : log1pf(-v)) : log1pf(-v);
            ov = (j == c) ? -1e30f : v;
        }
        float rs = lt, om = ov;
        #pragma unroll
        for (int o = 16; o > 0; o >>= 1) {
            rs += __shfl_xor_sync(0xffffffffu, rs, o);
            om  = fmaxf(om, __shfl_xor_sync(0xffffffffu, om, o));
        }
        if (lane == 0) { s_rowsum[c] = rs; s_q[c] = (pres && om < 0.6f) ? 1 : 0; }

        float x = (j < CC) ? s_G[(40+j)*41 + c] : -3.4e38f;
        float m = x;
        #pragma unroll
        for (int o = 16; o > 0; o >>= 1) m = fmaxf(m, __shfl_xor_sync(0xffffffffu, m, o));
        float e = (j < CC) ? expf(x - m) : 0.f;
        float ssum = e;
        #pragma unroll
        for (int o = 16; o > 0; o >>= 1) ssum += __shfl_xor_sync(0xffffffffu, ssum, o);
        float tt = 0.f;
        if (j < CC) {
            float pr = e * (1.f / ssum);
            tt = (j == c) ? fmaxf(logf(pr), -100.f) : fmaxf(log1pf(-pr), -100.f);
        }
        #pragma unroll
        for (int o = 16; o > 0; o >>= 1) tt += __shfl_xor_sync(0xffffffffu, tt, o);
        if (lane == 0) s_term[c] = -tt * (1.f / (float)CC);
    }
    __syncthreads();

    // ---- T1: accumulate batch-0 losses; compose fc1 norms ----
    if (tid < CC) {
        int j = tid;
        float ss = s_q[j]
            ? 0.9025f*s_n[2][j] + 0.095f*s_G[j*41 + j] + 0.0025f*s_n[0][j]
            : s_n[2][j];
        s_invc1[j] = 1.f / fmaxf(sqrtf(ss), 1e-12f);
    }
    if (tid == 0) {
        float tot = 0.f;
        for (int c = 0; c < CC; c++) tot += s_rowsum[c];
        s_acc[0] -= tot * (1.f / (float)(CC*CC));
        float ls = 0.f; int n = 0;
        for (int c = 0; c < CC; c++) if (s_q[c]) { ls += s_term[c]; n++; }
        s_acc[1] += ls;
        if (n > 0) s_acc[1] /= (float)n;      // divides ACCUMULATED value, per reference
    }
    __syncthreads();

    // ---- T2: batch-1 epilogue with EMA-composed cos dots ----
    if (wid < CC) {
        int c = wid, j = lane;
        bool pres = __ldg(&label[CC + c]) > 0.5f;
        float v = 1e-5f;
        if (j < CC) {
            float m1 = s_G[j*41 + 20 + c];
            float raw = s_q[j] ? fmaf(0.95f, m1, 0.05f * s_G[(20+j)*41 + 20 + c]) : m1;
            v = fabsf(raw * s_invf1[c] * s_invc1[j]);
            v = fminf(fmaxf(v, 1e-5f), 1.f - 1e-5f);
        }
        float lt = 0.f, ov = -1e30f;
        if (j < CC) {
            lt = (j == c) ? (pres ? logf(v) : log1pf(-v)) : log1pf(-v);
            ov = (j == c) ? -1e30f : v;
        }
        float rs = lt, om = ov;
        #pragma unroll
        for (int o = 16; o > 0; o >>= 1) {
            rs += __shfl_xor_sync(0xffffffffu, rs, o);
            om  = fmaxf(om, __shfl_xor_sync(0xffffffffu, om, o));
        }
        if (lane == 0) { s_rowsum[c] = rs; s_q1[c] = (pres && om < 0.6f) ? 1 : 0; }

        float x = (j < CC) ? s_G[(40+j)*41 + 20 + c] : -3.4e38f;
        float m = x;
        #pragma unroll
        for (int o = 16; o > 0; o >>= 1) m = fmaxf(m, __shfl_xor_sync(0xffffffffu, m, o));
        float e = (j < CC) ? expf(x - m) : 0.f;
        float ssum = e;
        #pragma unroll
        for (int o = 16; o > 0; o >>= 1) ssum += __shfl_xor_sync(0xffffffffu, ssum, o);
        float tt = 0.f;
        if (j < CC) {
            float pr = e * (1.f / ssum);
            tt = (j == c) ? fmaxf(logf(pr), -100.f) : fmaxf(log1pf(-pr), -100.f);
        }
        #pragma unroll
        for (int o = 16; o > 0; o >>= 1) tt += __shfl_xor_sync(0xffffffffu, tt, o);
        if (lane == 0) s_term[c] = -tt * (1.f / (float)CC);
    }
    __syncthreads();

    if (tid == 0) {
        float tot = 0.f;
        for (int c = 0; c < CC; c++) tot += s_rowsum[c];
        s_acc[0] -= tot * (1.f / (float)(CC*CC));
        float ls = 0.f; int n = 0;
        for (int c = 0; c < CC; c++) if (s_q1[c]) { ls += s_term[c]; n++; }
        s_acc[1] += ls;
        if (n > 0) s_acc[1] /= (float)n;
        out[0] = s_acc[0] + s_acc[1];
    }

    // ---- cleanup: restore zero-scratch invariant for next launch ----
    {
        float4 z4 = make_float4(0.f, 0.f, 0.f, 0.f);
        float4* w4 = (float4*)g_W;
        for (int i = tid; i < (BB*CC*FHW)/4; i += 640) w4[i] = z4;
        float4* f4 = (float4*)g_fsm;
        for (int i = tid; i < (BB*CC*DD)/4; i += 640) f4[i] = z4;
        if (tid < BB*CC) { g_cnt[tid] = 0; g_done[tid] = 0; }
        if (tid == 0) g_sync = 0;
    }
}

extern "C" void kernel_launch(void* const* d_in, const int* in_sizes, int n_in,
                              void* d_out, int out_size)
{
    (void)in_sizes; (void)n_in; (void)out_size;
    const float* fmap  = (const float*)d_in[0];
    const float* cam   = (const float*)d_in[1];
    const float* label = (const float*)d_in[2];
    const float* proj  = (const float*)d_in[3];
    const float* fc0   = (const float*)d_in[4];
    const float* hig   = (const float*)d_in[5];
    const float* low   = (const float*)d_in[6];
    const float* bg    = (const float*)d_in[7];
    float* out = (float*)d_out;

    k_pseudo    <<<BB*196, 256>>>(cam, label, hig, low, bg);
    k_topk_scan <<<BB*CC*NCH, 256>>>(cam, label);
    k_fsm       <<<BB*FH*2, 128>>>(fmap, label);
    k_loss2     <<<120, 640>>>(label, fc0, proj, out);
}